// round 10
// baseline (speedup 1.0000x reference)
#include <cuda_runtime.h>
#include <cstdint>

typedef unsigned int u32;
typedef unsigned short u16;

#define SEL   2
#define Bb    2
#define Cc    256
#define Nn    2304
#define Gg    8
#define CGd   16
#define INTER 128
#define EPSf  1e-5f
#define LOG2E 1.4426950408889634f

// ---------------- scratch ----------------
__device__ u16  g_xTh[SEL*Bb*Nn*Cc];        // [sb][n][c] bf16 hi (x transposed)
__device__ u16  g_xTl[SEL*Bb*Nn*Cc];        // lo
__device__ u16  g_thQ[SEL*Bb*Gg*Nn*32];     // [bg][n][16 hi | 16 lo], theta*log2e
__device__ u16  g_phK[SEL*Bb*Gg*Nn*32];     // [bg][n][16 hi | 16 lo], phi
__device__ u16  g_vH [SEL*Bb*Gg*CGd*Nn];    // [bg][d][n] hi
__device__ u16  g_vL [SEL*Bb*Gg*CGd*Nn];    // lo
__device__ u16  g_ocTh[SEL*Bb*Nn*INTER];    // [sb][n][i] attention out hi
__device__ u16  g_ocTl[SEL*Bb*Nn*INTER];    // lo
__device__ float g_wy  [SEL*Bb*Cc*Nn];
__device__ float g_mean[SEL*Cc];
__device__ float g_rstd[SEL*Cc];

// ---------------- helpers ----------------
__device__ __forceinline__ u32 smem_u32(const void* p) {
    u32 a;
    asm("{ .reg .u64 t; cvta.to.shared.u64 t, %1; cvt.u32.u64 %0, t; }" : "=r"(a) : "l"(p));
    return a;
}
__device__ __forceinline__ u32 cvt2bf(float hi, float lo) {
    u32 d; asm("cvt.rn.bf16x2.f32 %0, %1, %2;" : "=r"(d) : "f"(hi), "f"(lo)); return d;
}
__device__ __forceinline__ float bflo(u32 w) { return __uint_as_float(w << 16); }
__device__ __forceinline__ float bfhi(u32 w) { return __uint_as_float(w & 0xFFFF0000u); }

__device__ __forceinline__ void ldsm4(u32* r, u32 a) {
    asm volatile("ldmatrix.sync.aligned.m8n8.x4.shared.b16 {%0,%1,%2,%3}, [%4];"
        : "=r"(r[0]), "=r"(r[1]), "=r"(r[2]), "=r"(r[3]) : "r"(a));
}
__device__ __forceinline__ void ldsm2(u32* r, u32 a) {
    asm volatile("ldmatrix.sync.aligned.m8n8.x2.shared.b16 {%0,%1}, [%2];"
        : "=r"(r[0]), "=r"(r[1]) : "r"(a));
}
__device__ __forceinline__ void mma_bf16(float* c, const u32* a, const u32* b) {
    asm volatile("mma.sync.aligned.m16n8k16.row.col.f32.bf16.bf16.f32 "
        "{%0,%1,%2,%3}, {%4,%5,%6,%7}, {%8,%9}, {%0,%1,%2,%3};"
        : "+f"(c[0]), "+f"(c[1]), "+f"(c[2]), "+f"(c[3])
        : "r"(a[0]), "r"(a[1]), "r"(a[2]), "r"(a[3]), "r"(b[0]), "r"(b[1]));
}
__device__ __forceinline__ float exp2f_fast(float t) {
    float z = t + 12582912.0f;
    int   r = __float_as_int(z) - 0x4b400000;
    float f = t - (z - 12582912.0f);
    float p = 9.6181291e-3f;                 // degree-4 (rel err ~4e-5)
    p = fmaf(p, f, 5.5504109e-2f);
    p = fmaf(p, f, 2.4022651e-1f);
    p = fmaf(p, f, 6.9314718e-1f);
    p = fmaf(p, f, 1.0f);
    return __int_as_float(__float_as_int(p) + (r << 23));
}

// ---------------- Kernel 0: x -> transposed bf16 hi/lo [sb][n][c] ----------------
struct XArgs { const float* x[2]; };

__global__ __launch_bounds__(256) void xcvt_kernel(XArgs A)
{
    // grid (18, 4)
    int n0 = blockIdx.x * 128;
    int sb = blockIdx.y;
    int sel = sb >> 1, b = sb & 1;
    const float* x = A.x[sel] + (size_t)b * Cc * Nn;
    __shared__ float T[64][132];
    int tid = threadIdx.x;

    for (int c0 = 0; c0 < Cc; c0 += 64) {
        int nn = tid & 127, ch = tid >> 7;
        #pragma unroll 8
        for (int i = 0; i < 32; ++i)
            T[ch + 2*i][nn] = x[(size_t)(c0 + ch + 2*i) * Nn + n0 + nn];
        __syncthreads();
        int n = tid >> 1, kh = (tid & 1) * 32;
        u32 hb[16], lb[16];
        #pragma unroll
        for (int j = 0; j < 16; ++j) {
            float v0 = T[kh + 2*j][n], v1 = T[kh + 2*j + 1][n];
            u32 hh = cvt2bf(v1, v0);
            hb[j] = hh;
            lb[j] = cvt2bf(v1 - bfhi(hh), v0 - bflo(hh));
        }
        size_t off = ((size_t)sb * Nn + n0 + n) * Cc + c0 + kh;
        uint4* dh = (uint4*)(g_xTh + off);
        uint4* dl = (uint4*)(g_xTl + off);
        dh[0] = make_uint4(hb[0],hb[1],hb[2],hb[3]);
        dh[1] = make_uint4(hb[4],hb[5],hb[6],hb[7]);
        dh[2] = make_uint4(hb[8],hb[9],hb[10],hb[11]);
        dh[3] = make_uint4(hb[12],hb[13],hb[14],hb[15]);
        dl[0] = make_uint4(lb[0],lb[1],lb[2],lb[3]);
        dl[1] = make_uint4(lb[4],lb[5],lb[6],lb[7]);
        dl[2] = make_uint4(lb[8],lb[9],lb[10],lb[11]);
        dl[3] = make_uint4(lb[12],lb[13],lb[14],lb[15]);
        __syncthreads();
    }
}

// ---------------- Kernel 1: grouped projections via bf16 mma ----------------
struct PjArgs {
    const float* w[2][3];      // [sel][theta, phi, g]
    const float* bias[2][3];
};

__global__ __launch_bounds__(128) void projmma_kernel(PjArgs A)
{
    // grid (18, 6, 4)
    __shared__ __align__(16) union {
        struct {
            u16 Ah[64*40], Al[64*40];     // [j][k-chunk 32 + pad]
            u16 Bh[128*40], Bl[128*40];   // [n][k]
        } m;
        float Cd[64*132];
    } SM;

    int tid = threadIdx.x, lane = tid & 31, wid = tid >> 5;
    int n0 = blockIdx.x * 128;
    int jt = blockIdx.y;
    int sb = blockIdx.z, sel = sb >> 1;
    int p  = jt >> 1;
    int g0 = (jt & 1) * 4;

    const float* wsrc = A.w[sel][p] + (size_t)(g0 * CGd) * Cc;
    const u16* xh = g_xTh + (size_t)sb * Nn * Cc;
    const u16* xl = g_xTl + (size_t)sb * Nn * Cc;

    float C[16][4];
    #pragma unroll
    for (int i = 0; i < 16; ++i)
        #pragma unroll
        for (int q = 0; q < 4; ++q) C[i][q] = 0.f;

    u32 AhB = smem_u32(SM.m.Ah), AlB = smem_u32(SM.m.Al);
    u32 BhB = smem_u32(SM.m.Bh), BlB = smem_u32(SM.m.Bl);

    int ar  = (lane & 7) + ((lane >> 3) & 1) * 8;
    int acb = (lane >> 4) * 16;
    int brow = (lane & 7) + ((lane >> 4) & 1) * 8;
    int bcb  = ((lane >> 3) & 1) * 16;

    for (int c0 = 0; c0 < Cc; c0 += 32) {
        {
            int j = tid >> 1, kh2 = (tid & 1) * 16;
            const float* wr = wsrc + (size_t)j * Cc + c0 + kh2;
            u32 hb[8], lb[8];
            #pragma unroll
            for (int q = 0; q < 8; ++q) {
                float v0 = wr[2*q], v1 = wr[2*q + 1];
                u32 hh = cvt2bf(v1, v0);
                hb[q] = hh;
                lb[q] = cvt2bf(v1 - bfhi(hh), v0 - bflo(hh));
            }
            uint4* dh = (uint4*)(SM.m.Ah + j * 40 + kh2);
            uint4* dl = (uint4*)(SM.m.Al + j * 40 + kh2);
            dh[0] = make_uint4(hb[0],hb[1],hb[2],hb[3]);
            dh[1] = make_uint4(hb[4],hb[5],hb[6],hb[7]);
            dl[0] = make_uint4(lb[0],lb[1],lb[2],lb[3]);
            dl[1] = make_uint4(lb[4],lb[5],lb[6],lb[7]);
        }
        {
            size_t off = (size_t)(n0 + tid) * Cc + c0;
            const uint4* sh = (const uint4*)(xh + off);
            const uint4* sl = (const uint4*)(xl + off);
            uint4* dh = (uint4*)(SM.m.Bh + tid * 40);
            uint4* dl = (uint4*)(SM.m.Bl + tid * 40);
            dh[0]=sh[0]; dh[1]=sh[1]; dh[2]=sh[2]; dh[3]=sh[3];
            dl[0]=sl[0]; dl[1]=sl[1]; dl[2]=sl[2]; dl[3]=sl[3];
        }
        __syncthreads();

        #pragma unroll
        for (int kk = 0; kk < 2; ++kk) {
            u32 ah[4], al[4];
            u32 aoff = (u32)(wid*16 + ar) * 80 + kk*32 + acb;
            ldsm4(ah, AhB + aoff);
            ldsm4(al, AlB + aoff);
            #pragma unroll
            for (int nn = 0; nn < 8; ++nn) {
                u32 bh[4], bl[4];
                u32 boff = (u32)(nn*16 + brow) * 80 + kk*32 + bcb;
                ldsm4(bh, BhB + boff);
                ldsm4(bl, BlB + boff);
                mma_bf16(C[2*nn],   ah, bh);
                mma_bf16(C[2*nn],   al, bh);
                mma_bf16(C[2*nn],   ah, bl);
                mma_bf16(C[2*nn+1], ah, bh+2);
                mma_bf16(C[2*nn+1], al, bh+2);
                mma_bf16(C[2*nn+1], ah, bl+2);
            }
        }
        __syncthreads();
    }

    {
        int gq = lane >> 2, tg = lane & 3;
        #pragma unroll
        for (int nf = 0; nf < 16; ++nf) {
            int r = wid*16 + gq, col = nf*8 + 2*tg;
            *(float2*)&SM.Cd[r*132 + col]       = make_float2(C[nf][0], C[nf][1]);
            *(float2*)&SM.Cd[(r+8)*132 + col]   = make_float2(C[nf][2], C[nf][3]);
        }
    }
    __syncthreads();

    if (p < 2) {
        const float* bias = A.bias[sel][p];
        #pragma unroll
        for (int gg = 0; gg < 4; ++gg) {
            int gabs = g0 + gg;
            int bg = sb * Gg + gabs;
            u32 hb[8], lb[8];
            #pragma unroll
            for (int q = 0; q < 8; ++q) {
                float v0 = SM.Cd[(gg*16 + 2*q)*132 + tid]   + bias[gabs*CGd + 2*q];
                float v1 = SM.Cd[(gg*16 + 2*q+1)*132 + tid] + bias[gabs*CGd + 2*q + 1];
                if (p == 0) { v0 *= LOG2E; v1 *= LOG2E; }
                u32 hh = cvt2bf(v1, v0);
                hb[q] = hh;
                lb[q] = cvt2bf(v1 - bfhi(hh), v0 - bflo(hh));
            }
            u16* dst = (p == 0 ? g_thQ : g_phK) + (size_t)(bg * Nn + n0 + tid) * 32;
            uint4* d4 = (uint4*)dst;
            d4[0] = make_uint4(hb[0],hb[1],hb[2],hb[3]);
            d4[1] = make_uint4(hb[4],hb[5],hb[6],hb[7]);
            d4[2] = make_uint4(lb[0],lb[1],lb[2],lb[3]);
            d4[3] = make_uint4(lb[4],lb[5],lb[6],lb[7]);
        }
    } else {
        const float* bias = A.bias[sel][2];
        int half = tid >> 6, np = tid & 63;
        #pragma unroll 4
        for (int rr = 0; rr < 32; ++rr) {
            int j = rr*2 + half;
            int gabs = g0 + (j >> 4), d = j & 15;
            float bv = bias[gabs*CGd + d];
            float v0 = SM.Cd[j*132 + 2*np]     + bv;
            float v1 = SM.Cd[j*132 + 2*np + 1] + bv;
            u32 hh = cvt2bf(v1, v0);
            size_t off = ((size_t)(sb*Gg + gabs)*CGd + d) * Nn + n0 + 2*np;
            *(u32*)(g_vH + off) = hh;
            *(u32*)(g_vL + off) = cvt2bf(v1 - bfhi(hh), v0 - bflo(hh));
        }
    }
}

// ---------------- Kernel 2: bf16 mma flash attention (M-tile 64) ----------------
#define QLD 40
#define VLD 136
#define OQ  0
#define OK  5120
#define OVH 15360
#define OVL 21888
#define SMSZ 26240

__global__ __launch_bounds__(128, 5) void attn_mma_kernel()
{
    __shared__ __align__(16) char SM[SMSZ];
    u16* Qs = (u16*)(SM + OQ);
    u16* Ks = (u16*)(SM + OK);
    u16* VHs = (u16*)(SM + OVH);
    u16* VLs = (u16*)(SM + OVL);

    int tid = threadIdx.x, lane = tid & 31, wid = tid >> 5;
    int g = blockIdx.y, sbz = blockIdx.z;
    int bg = sbz * Gg + g;
    int n0 = blockIdx.x * 64;

    const u16* thq = g_thQ + (size_t)bg * Nn * 32;
    const u16* phk = g_phK + (size_t)bg * Nn * 32;
    const u16* vh  = g_vH + (size_t)bg * CGd * Nn;
    const u16* vl  = g_vL + (size_t)bg * CGd * Nn;

    // Q fill: 64 rows
    if (tid < 64) {
        const uint4* src = (const uint4*)(thq + (size_t)(n0 + tid) * 32);
        uint4* dst = (uint4*)(Qs + tid * QLD);
        dst[0] = src[0]; dst[1] = src[1]; dst[2] = src[2]; dst[3] = src[3];
    }
    // VH constant rows 16..23 (row 16 = ones)
    #pragma unroll
    for (int i = 0; i < 8; ++i) {
        int r = 16 + i;
        VHs[r * VLD + tid] = (r == 16) ? (u16)0x3F80 : (u16)0;
    }
    __syncthreads();

    u32 SMB = smem_u32(SM);
    u32 QB = SMB + OQ, KB = SMB + OK, VHB = SMB + OVH, VLB = SMB + OVL;

    // Q A-fragments: each warp owns 16 query rows
    u32 qh[4], ql[4];
    {
        int ar  = (lane & 7) + ((lane >> 3) & 1) * 8;
        int acb = (lane >> 4) * 16;
        u32 ad = QB + (u32)(wid * 16 + ar) * 80 + acb;
        ldsm4(qh, ad);
        ldsm4(ql, ad + 32);
    }

    float O[3][4];
    #pragma unroll
    for (int nt = 0; nt < 3; ++nt)
        #pragma unroll
        for (int q = 0; q < 4; ++q) O[nt][q] = 0.f;

    int krow = (lane & 7) + ((lane >> 4) & 1) * 8;
    int kcb  = ((lane >> 3) & 1) * 16;
    int vrow = (lane & 7);
    int vcb  = ((lane >> 3) & 1) * 16;

    for (int t = 0; t < 18; ++t) {
        int t0 = t * 128;
        {
            const uint4* src = (const uint4*)(phk + (size_t)(t0 + tid) * 32);
            uint4* dst = (uint4*)(Ks + tid * QLD);
            dst[0] = src[0]; dst[1] = src[1]; dst[2] = src[2]; dst[3] = src[3];
        }
        {
            int d = tid >> 3, blk = (tid & 7) * 16;
            const uint4* sh = (const uint4*)(vh + (size_t)d * Nn + t0 + blk);
            const uint4* sl = (const uint4*)(vl + (size_t)d * Nn + t0 + blk);
            uint4* dh = (uint4*)(VHs + d * VLD + blk);
            uint4* dl = (uint4*)(VLs + d * VLD + blk);
            dh[0] = sh[0]; dh[1] = sh[1];
            dl[0] = sl[0]; dl[1] = sl[1];
        }
        __syncthreads();

        #pragma unroll 2
        for (int c = 0; c < 8; ++c) {
            u32 khb4[4], klb4[4];
            {
                u32 a = KB + (u32)(c * 16 + krow) * 80 + kcb;
                ldsm4(khb4, a);
                ldsm4(klb4, a + 32);
            }
            float C[2][4];
            #pragma unroll
            for (int s = 0; s < 2; ++s) {
                C[s][0] = 0.f; C[s][1] = 0.f; C[s][2] = 0.f; C[s][3] = 0.f;
                mma_bf16(C[s], qh, khb4 + 2*s);
                mma_bf16(C[s], qh, klb4 + 2*s);
                mma_bf16(C[s], ql, khb4 + 2*s);
            }
            u32 pha[4], pla[4];
            #pragma unroll
            for (int s = 0; s < 2; ++s) {
                float p0 = exp2f_fast(C[s][0]);
                float p1 = exp2f_fast(C[s][1]);
                float p2 = exp2f_fast(C[s][2]);
                float p3 = exp2f_fast(C[s][3]);
                u32 w01 = cvt2bf(p1, p0);
                u32 w23 = cvt2bf(p3, p2);
                pha[2*s]     = w01;
                pha[2*s + 1] = w23;
                pla[2*s]     = cvt2bf(p1 - bfhi(w01), p0 - bflo(w01));
                pla[2*s + 1] = cvt2bf(p3 - bfhi(w23), p2 - bflo(w23));
            }
            u32 vhbf[3][2], vlbf[2][2];
            {
                u32 vbase = (u32)vrow * 272 + (u32)vcb + (u32)c * 32;
                #pragma unroll
                for (int nt = 0; nt < 3; ++nt)
                    ldsm2(vhbf[nt], VHB + vbase + (u32)nt * 8 * 272);
                #pragma unroll
                for (int nt = 0; nt < 2; ++nt)
                    ldsm2(vlbf[nt], VLB + vbase + (u32)nt * 8 * 272);
            }
            #pragma unroll
            for (int nt = 0; nt < 3; ++nt) {
                mma_bf16(O[nt], pha, vhbf[nt]);
                mma_bf16(O[nt], pla, vhbf[nt]);
            }
            #pragma unroll
            for (int nt = 0; nt < 2; ++nt)
                mma_bf16(O[nt], pha, vlbf[nt]);
        }
        __syncthreads();
    }

    // Epilogue: dump O to smem (stride 26), normalize, emit bf16 hi/lo [n][i]
    float* Es = (float*)(SM + OK);
    {
        int gq = lane >> 2, tg = lane & 3;
        #pragma unroll
        for (int nt = 0; nt < 3; ++nt) {
            int r = wid * 16 + gq;
            int col = nt * 8 + 2 * tg;
            Es[r * 26 + col]           = O[nt][0];
            Es[r * 26 + col + 1]       = O[nt][1];
            Es[(r + 8) * 26 + col]     = O[nt][2];
            Es[(r + 8) * 26 + col + 1] = O[nt][3];
        }
    }
    __syncthreads();
    if (tid < 64) {
        float inv = 1.0f / Es[tid * 26 + 16];
        u32 hb[8], lb[8];
        #pragma unroll
        for (int q = 0; q < 8; ++q) {
            float v0 = Es[tid * 26 + 2*q]     * inv;
            float v1 = Es[tid * 26 + 2*q + 1] * inv;
            u32 hh = cvt2bf(v1, v0);
            hb[q] = hh;
            lb[q] = cvt2bf(v1 - bfhi(hh), v0 - bflo(hh));
        }
        size_t off = ((size_t)sbz * Nn + n0 + tid) * INTER + g * CGd;
        uint4* dh = (uint4*)(g_ocTh + off);
        uint4* dl = (uint4*)(g_ocTl + off);
        dh[0] = make_uint4(hb[0],hb[1],hb[2],hb[3]);
        dh[1] = make_uint4(hb[4],hb[5],hb[6],hb[7]);
        dl[0] = make_uint4(lb[0],lb[1],lb[2],lb[3]);
        dl[1] = make_uint4(lb[4],lb[5],lb[6],lb[7]);
    }
}

// ---------------- Kernel 3: W conv via bf16 mma (n-tile 64) ----------------
struct WcArgs { const float* Ww[2]; const float* Wb[2]; };

__global__ __launch_bounds__(128) void wconvmma_kernel(WcArgs A)
{
    // grid (36, 4, 4): n-tile 64, o-tile 64, sb
    __shared__ __align__(16) struct {
        u16 Ah[64*40], Al[64*40];
        u16 Bh[64*40], Bl[64*40];
    } SM;

    int tid = threadIdx.x, lane = tid & 31, wid = tid >> 5;
    int n0 = blockIdx.x * 64;
    int o0 = blockIdx.y * 64;
    int sb = blockIdx.z, sel = sb >> 1;

    const float* Ww = A.Ww[sel];
    const u16* och = g_ocTh + (size_t)sb * Nn * INTER;
    const u16* ocl = g_ocTl + (size_t)sb * Nn * INTER;

    float C[8][4];
    #pragma unroll
    for (int i = 0; i < 8; ++i)
        #pragma unroll
        for (int q = 0; q < 4; ++q) C[i][q] = 0.f;

    u32 AhB = smem_u32(SM.Ah), AlB = smem_u32(SM.Al);
    u32 BhB = smem_u32(SM.Bh), BlB = smem_u32(SM.Bl);

    int ar  = (lane & 7) + ((lane >> 3) & 1) * 8;
    int acb = (lane >> 4) * 16;
    int brow = (lane & 7) + ((lane >> 4) & 1) * 8;
    int bcb  = ((lane >> 3) & 1) * 16;

    for (int c0 = 0; c0 < INTER; c0 += 32) {
        {
            int j = tid >> 1, kh2 = (tid & 1) * 16;
            const float* wr = Ww + (size_t)(o0 + j) * INTER + c0 + kh2;
            u32 hb[8], lb[8];
            #pragma unroll
            for (int q = 0; q < 8; ++q) {
                float v0 = wr[2*q], v1 = wr[2*q + 1];
                u32 hh = cvt2bf(v1, v0);
                hb[q] = hh;
                lb[q] = cvt2bf(v1 - bfhi(hh), v0 - bflo(hh));
            }
            uint4* dh = (uint4*)(SM.Ah + j * 40 + kh2);
            uint4* dl = (uint4*)(SM.Al + j * 40 + kh2);
            dh[0] = make_uint4(hb[0],hb[1],hb[2],hb[3]);
            dh[1] = make_uint4(hb[4],hb[5],hb[6],hb[7]);
            dl[0] = make_uint4(lb[0],lb[1],lb[2],lb[3]);
            dl[1] = make_uint4(lb[4],lb[5],lb[6],lb[7]);
        }
        {
            int row = tid >> 1;
            size_t off = (size_t)(n0 + row) * INTER + c0;
            if (tid & 1) {
                const uint4* sl = (const uint4*)(ocl + off);
                uint4* dl = (uint4*)(SM.Bl + row * 40);
                dl[0] = sl[0]; dl[1] = sl[1];
                dl[2] = sl[2]; dl[3] = sl[3];
            } else {
                const uint4* sh = (const uint4*)(och + off);
                uint4* dh = (uint4*)(SM.Bh + row * 40);
                dh[0] = sh[0]; dh[1] = sh[1];
                dh[2] = sh[2]; dh[3] = sh[3];
            }
        }
        __syncthreads();

        #pragma unroll
        for (int kk = 0; kk < 2; ++kk) {
            u32 ah[4], al[4];
            u32 aoff = (u32)(wid*16 + ar) * 80 + kk*32 + acb;
            ldsm4(ah, AhB + aoff);
            ldsm4(al, AlB + aoff);
            #pragma unroll
            for (int nn = 0; nn < 4; ++nn) {
                u32 bh[4], bl[4];
                u32 boff = (u32)(nn*16 + brow) * 80 + kk*32 + bcb;
                ldsm4(bh, BhB + boff);
                ldsm4(bl, BlB + boff);
                mma_bf16(C[2*nn],   ah, bh);
                mma_bf16(C[2*nn],   al, bh);
                mma_bf16(C[2*nn],   ah, bl);
                mma_bf16(C[2*nn+1], ah, bh+2);
                mma_bf16(C[2*nn+1], al, bh+2);
                mma_bf16(C[2*nn+1], ah, bl+2);
            }
        }
        __syncthreads();
    }

    {
        const float* Wb = A.Wb[sel];
        int gq = lane >> 2, tg = lane & 3;
        int o_r = o0 + wid*16 + gq;
        float b0 = Wb[o_r], b1 = Wb[o_r + 8];
        #pragma unroll
        for (int nf = 0; nf < 8; ++nf) {
            int n_c = n0 + nf*8 + 2*tg;
            *(float2*)&g_wy[((size_t)sb*Cc + o_r) * Nn + n_c] =
                make_float2(C[nf][0] + b0, C[nf][1] + b0);
            *(float2*)&g_wy[((size_t)sb*Cc + o_r + 8) * Nn + n_c] =
                make_float2(C[nf][2] + b1, C[nf][3] + b1);
        }
    }
}

// ---------------- Kernel 4: BN stats ----------------
__global__ __launch_bounds__(256) void stats_kernel()
{
    int sel = blockIdx.x / Cc;
    int o   = blockIdx.x % Cc;
    int tid = threadIdx.x;
    const float4* r0 = (const float4*)(g_wy + ((size_t)(sel*Bb + 0) * Cc + o) * Nn);
    const float4* r1 = (const float4*)(g_wy + ((size_t)(sel*Bb + 1) * Cc + o) * Nn);

    float s = 0.f, s2 = 0.f;
    for (int i = tid; i < Nn/4; i += 256) {
        float4 a = r0[i], c = r1[i];
        s += a.x + a.y + a.z + a.w;
        s += c.x + c.y + c.z + c.w;
        s2 = fmaf(a.x, a.x, s2); s2 = fmaf(a.y, a.y, s2);
        s2 = fmaf(a.z, a.z, s2); s2 = fmaf(a.w, a.w, s2);
        s2 = fmaf(c.x, c.x, s2); s2 = fmaf(c.y, c.y, s2);
        s2 = fmaf(c.z, c.z, s2); s2 = fmaf(c.w, c.w, s2);
    }
    __shared__ float sh[256], sh2[256];
    sh[tid] = s; sh2[tid] = s2;
    __syncthreads();
    for (int st = 128; st > 0; st >>= 1) {
        if (tid < st) { sh[tid] += sh[tid + st]; sh2[tid] += sh2[tid + st]; }
        __syncthreads();
    }
    if (tid == 0) {
        float mean = sh[0] * (1.0f / (Bb * Nn));
        float var  = sh2[0] * (1.0f / (Bb * Nn)) - mean * mean;
        g_mean[blockIdx.x] = mean;
        g_rstd[blockIdx.x] = rsqrtf(var + EPSf);
    }
}

// ---------------- Kernel 5: BN apply + residual + ReLU ----------------
struct ApplyArgs {
    const float* x[2];
    const float* gam[2]; const float* bet[2];
};

__global__ __launch_bounds__(256) void apply_kernel(ApplyArgs A, float* __restrict__ out)
{
    int i4 = blockIdx.x * 256 + threadIdx.x;
    int idx = i4 * 4;
    int per = Bb * Cc * Nn;
    int sel = idx / per;
    int loc = idx - sel * per;
    int o   = (loc / Nn) % Cc;
    float m  = g_mean[sel*Cc + o];
    float rs = g_rstd[sel*Cc + o];
    float ga = A.gam[sel][o], be = A.bet[sel][o];
    float4 wv = *(const float4*)(g_wy + idx);
    float4 xv = *(const float4*)(A.x[sel] + loc);
    float4 r;
    r.x = fmaxf(fmaf((wv.x - m) * rs, ga, be) + xv.x, 0.f);
    r.y = fmaxf(fmaf((wv.y - m) * rs, ga, be) + xv.y, 0.f);
    r.z = fmaxf(fmaf((wv.z - m) * rs, ga, be) + xv.z, 0.f);
    r.w = fmaxf(fmaf((wv.w - m) * rs, ga, be) + xv.w, 0.f);
    *(float4*)(out + idx) = r;
}

// ---------------- launch ----------------
extern "C" void kernel_launch(void* const* d_in, const int* in_sizes, int n_in,
                              void* d_out, int out_size)
{
    XArgs X; PjArgs P; WcArgs W; ApplyArgs AP;
    for (int s = 0; s < 2; ++s) {
        X.x[s] = (const float*)d_in[s];
        P.w[s][0]    = (const float*)d_in[2 + s*10 + 2];   // theta_w
        P.bias[s][0] = (const float*)d_in[2 + s*10 + 3];
        P.w[s][1]    = (const float*)d_in[2 + s*10 + 4];   // phi_w
        P.bias[s][1] = (const float*)d_in[2 + s*10 + 5];
        P.w[s][2]    = (const float*)d_in[2 + s*10 + 0];   // g_w
        P.bias[s][2] = (const float*)d_in[2 + s*10 + 1];
        W.Ww[s] = (const float*)d_in[2 + s*10 + 6];
        W.Wb[s] = (const float*)d_in[2 + s*10 + 7];
        AP.x[s]   = (const float*)d_in[s];
        AP.gam[s] = (const float*)d_in[2 + s*10 + 8];
        AP.bet[s] = (const float*)d_in[2 + s*10 + 9];
    }

    xcvt_kernel    <<<dim3(18, 4), 256>>>(X);
    projmma_kernel <<<dim3(18, 6, 4), 128>>>(P);
    attn_mma_kernel<<<dim3(36, Gg, SEL*Bb), 128>>>();
    wconvmma_kernel<<<dim3(36, 4, 4), 128>>>(W);
    stats_kernel   <<<SEL*Cc, 256>>>();
    apply_kernel   <<<(SEL*Bb*Cc*Nn)/1024, 256>>>(AP, (float*)d_out);
}

// round 12
// speedup vs baseline: 1.0366x; 1.0366x over previous
#include <cuda_runtime.h>
#include <cstdint>

typedef unsigned int u32;
typedef unsigned short u16;

#define SEL   2
#define Bb    2
#define Cc    256
#define Nn    2304
#define Gg    8
#define CGd   16
#define INTER 128
#define EPSf  1e-5f
#define LOG2E 1.4426950408889634f

// ---------------- scratch ----------------
__device__ __align__(16) u16  g_xTh[SEL*Bb*Nn*Cc];
__device__ __align__(16) u16  g_xTl[SEL*Bb*Nn*Cc];
__device__ __align__(16) u16  g_thQ[SEL*Bb*Gg*Nn*32];
__device__ __align__(16) u16  g_phK[SEL*Bb*Gg*Nn*32];
__device__ __align__(16) u16  g_vH [SEL*Bb*Gg*CGd*Nn];
__device__ __align__(16) u16  g_vL [SEL*Bb*Gg*CGd*Nn];
__device__ __align__(16) u16  g_ocTh[SEL*Bb*Nn*INTER];
__device__ __align__(16) u16  g_ocTl[SEL*Bb*Nn*INTER];
__device__ float g_wy  [SEL*Bb*Cc*Nn];
__device__ float g_mean[SEL*Cc];
__device__ float g_rstd[SEL*Cc];

// ---------------- helpers ----------------
__device__ __forceinline__ u32 smem_u32(const void* p) {
    u32 a;
    asm("{ .reg .u64 t; cvta.to.shared.u64 t, %1; cvt.u32.u64 %0, t; }" : "=r"(a) : "l"(p));
    return a;
}
__device__ __forceinline__ u32 cvt2bf(float hi, float lo) {
    u32 d; asm("cvt.rn.bf16x2.f32 %0, %1, %2;" : "=r"(d) : "f"(hi), "f"(lo)); return d;
}
__device__ __forceinline__ float bflo(u32 w) { return __uint_as_float(w << 16); }
__device__ __forceinline__ float bfhi(u32 w) { return __uint_as_float(w & 0xFFFF0000u); }

__device__ __forceinline__ void ldsm4(u32* r, u32 a) {
    asm volatile("ldmatrix.sync.aligned.m8n8.x4.shared.b16 {%0,%1,%2,%3}, [%4];"
        : "=r"(r[0]), "=r"(r[1]), "=r"(r[2]), "=r"(r[3]) : "r"(a));
}
__device__ __forceinline__ void ldsm2(u32* r, u32 a) {
    asm volatile("ldmatrix.sync.aligned.m8n8.x2.shared.b16 {%0,%1}, [%2];"
        : "=r"(r[0]), "=r"(r[1]) : "r"(a));
}
__device__ __forceinline__ void mma_bf16(float* c, const u32* a, const u32* b) {
    asm volatile("mma.sync.aligned.m16n8k16.row.col.f32.bf16.bf16.f32 "
        "{%0,%1,%2,%3}, {%4,%5,%6,%7}, {%8,%9}, {%0,%1,%2,%3};"
        : "+f"(c[0]), "+f"(c[1]), "+f"(c[2]), "+f"(c[3])
        : "r"(a[0]), "r"(a[1]), "r"(a[2]), "r"(a[3]), "r"(b[0]), "r"(b[1]));
}
__device__ __forceinline__ void cpa16(u32 dst, const void* src) {
    asm volatile("cp.async.cg.shared.global [%0], [%1], 16;" :: "r"(dst), "l"(src));
}
#define CPA_COMMIT() asm volatile("cp.async.commit_group;" ::: "memory")
#define CPA_WAIT0()  asm volatile("cp.async.wait_group 0;" ::: "memory")

__device__ __forceinline__ float exp2f_fast(float t) {
    float z = t + 12582912.0f;
    int   r = __float_as_int(z) - 0x4b400000;
    float f = t - (z - 12582912.0f);
    float p = 9.6181291e-3f;
    p = fmaf(p, f, 5.5504109e-2f);
    p = fmaf(p, f, 2.4022651e-1f);
    p = fmaf(p, f, 6.9314718e-1f);
    p = fmaf(p, f, 1.0f);
    return __int_as_float(__float_as_int(p) + (r << 23));
}

// ---------------- Kernel 0: x -> transposed bf16 hi/lo [sb][n][c] ----------------
struct XArgs { const float* x[2]; };

__global__ __launch_bounds__(256) void xcvt_kernel(XArgs A)
{
    int n0 = blockIdx.x * 128;
    int sb = blockIdx.y;
    int sel = sb >> 1, b = sb & 1;
    const float* x = A.x[sel] + (size_t)b * Cc * Nn;
    __shared__ float T[64][132];
    int tid = threadIdx.x;

    for (int c0 = 0; c0 < Cc; c0 += 64) {
        int nn = tid & 127, ch = tid >> 7;
        #pragma unroll 8
        for (int i = 0; i < 32; ++i)
            T[ch + 2*i][nn] = x[(size_t)(c0 + ch + 2*i) * Nn + n0 + nn];
        __syncthreads();
        int n = tid >> 1, kh = (tid & 1) * 32;
        u32 hb[16], lb[16];
        #pragma unroll
        for (int j = 0; j < 16; ++j) {
            float v0 = T[kh + 2*j][n], v1 = T[kh + 2*j + 1][n];
            u32 hh = cvt2bf(v1, v0);
            hb[j] = hh;
            lb[j] = cvt2bf(v1 - bfhi(hh), v0 - bflo(hh));
        }
        size_t off = ((size_t)sb * Nn + n0 + n) * Cc + c0 + kh;
        uint4* dh = (uint4*)(g_xTh + off);
        uint4* dl = (uint4*)(g_xTl + off);
        dh[0] = make_uint4(hb[0],hb[1],hb[2],hb[3]);
        dh[1] = make_uint4(hb[4],hb[5],hb[6],hb[7]);
        dh[2] = make_uint4(hb[8],hb[9],hb[10],hb[11]);
        dh[3] = make_uint4(hb[12],hb[13],hb[14],hb[15]);
        dl[0] = make_uint4(lb[0],lb[1],lb[2],lb[3]);
        dl[1] = make_uint4(lb[4],lb[5],lb[6],lb[7]);
        dl[2] = make_uint4(lb[8],lb[9],lb[10],lb[11]);
        dl[3] = make_uint4(lb[12],lb[13],lb[14],lb[15]);
        __syncthreads();
    }
}

// ---------------- Kernel 1: grouped projections via bf16 mma ----------------
struct PjArgs {
    const float* w[2][3];
    const float* bias[2][3];
};

__global__ __launch_bounds__(128) void projmma_kernel(PjArgs A)
{
    __shared__ __align__(16) union {
        struct {
            u16 Ah[64*40], Al[64*40];
            u16 Bh[128*40], Bl[128*40];
        } m;
        float Cd[64*132];
    } SM;

    int tid = threadIdx.x, lane = tid & 31, wid = tid >> 5;
    int n0 = blockIdx.x * 128;
    int jt = blockIdx.y;
    int sb = blockIdx.z, sel = sb >> 1;
    int p  = jt >> 1;
    int g0 = (jt & 1) * 4;

    const float* wsrc = A.w[sel][p] + (size_t)(g0 * CGd) * Cc;
    const u16* xh = g_xTh + (size_t)sb * Nn * Cc;
    const u16* xl = g_xTl + (size_t)sb * Nn * Cc;

    float C[16][4];
    #pragma unroll
    for (int i = 0; i < 16; ++i)
        #pragma unroll
        for (int q = 0; q < 4; ++q) C[i][q] = 0.f;

    u32 AhB = smem_u32(SM.m.Ah), AlB = smem_u32(SM.m.Al);
    u32 BhB = smem_u32(SM.m.Bh), BlB = smem_u32(SM.m.Bl);

    int ar  = (lane & 7) + ((lane >> 3) & 1) * 8;
    int acb = (lane >> 4) * 16;
    int brow = (lane & 7) + ((lane >> 4) & 1) * 8;
    int bcb  = ((lane >> 3) & 1) * 16;

    for (int c0 = 0; c0 < Cc; c0 += 32) {
        {
            int j = tid >> 1, kh2 = (tid & 1) * 16;
            const float* wr = wsrc + (size_t)j * Cc + c0 + kh2;
            u32 hb[8], lb[8];
            #pragma unroll
            for (int q = 0; q < 8; ++q) {
                float v0 = wr[2*q], v1 = wr[2*q + 1];
                u32 hh = cvt2bf(v1, v0);
                hb[q] = hh;
                lb[q] = cvt2bf(v1 - bfhi(hh), v0 - bflo(hh));
            }
            uint4* dh = (uint4*)(SM.m.Ah + j * 40 + kh2);
            uint4* dl = (uint4*)(SM.m.Al + j * 40 + kh2);
            dh[0] = make_uint4(hb[0],hb[1],hb[2],hb[3]);
            dh[1] = make_uint4(hb[4],hb[5],hb[6],hb[7]);
            dl[0] = make_uint4(lb[0],lb[1],lb[2],lb[3]);
            dl[1] = make_uint4(lb[4],lb[5],lb[6],lb[7]);
        }
        {
            size_t off = (size_t)(n0 + tid) * Cc + c0;
            const uint4* sh = (const uint4*)(xh + off);
            const uint4* sl = (const uint4*)(xl + off);
            uint4* dh = (uint4*)(SM.m.Bh + tid * 40);
            uint4* dl = (uint4*)(SM.m.Bl + tid * 40);
            dh[0]=sh[0]; dh[1]=sh[1]; dh[2]=sh[2]; dh[3]=sh[3];
            dl[0]=sl[0]; dl[1]=sl[1]; dl[2]=sl[2]; dl[3]=sl[3];
        }
        __syncthreads();

        #pragma unroll
        for (int kk = 0; kk < 2; ++kk) {
            u32 ah[4], al[4];
            u32 aoff = (u32)(wid*16 + ar) * 80 + kk*32 + acb;
            ldsm4(ah, AhB + aoff);
            ldsm4(al, AlB + aoff);
            #pragma unroll
            for (int nn = 0; nn < 8; ++nn) {
                u32 bh[4], bl[4];
                u32 boff = (u32)(nn*16 + brow) * 80 + kk*32 + bcb;
                ldsm4(bh, BhB + boff);
                ldsm4(bl, BlB + boff);
                mma_bf16(C[2*nn],   ah, bh);
                mma_bf16(C[2*nn],   al, bh);
                mma_bf16(C[2*nn],   ah, bl);
                mma_bf16(C[2*nn+1], ah, bh+2);
                mma_bf16(C[2*nn+1], al, bh+2);
                mma_bf16(C[2*nn+1], ah, bl+2);
            }
        }
        __syncthreads();
    }

    {
        int gq = lane >> 2, tg = lane & 3;
        #pragma unroll
        for (int nf = 0; nf < 16; ++nf) {
            int r = wid*16 + gq, col = nf*8 + 2*tg;
            *(float2*)&SM.Cd[r*132 + col]       = make_float2(C[nf][0], C[nf][1]);
            *(float2*)&SM.Cd[(r+8)*132 + col]   = make_float2(C[nf][2], C[nf][3]);
        }
    }
    __syncthreads();

    if (p < 2) {
        const float* bias = A.bias[sel][p];
        #pragma unroll
        for (int gg = 0; gg < 4; ++gg) {
            int gabs = g0 + gg;
            int bg = sb * Gg + gabs;
            u32 hb[8], lb[8];
            #pragma unroll
            for (int q = 0; q < 8; ++q) {
                float v0 = SM.Cd[(gg*16 + 2*q)*132 + tid]   + bias[gabs*CGd + 2*q];
                float v1 = SM.Cd[(gg*16 + 2*q+1)*132 + tid] + bias[gabs*CGd + 2*q + 1];
                if (p == 0) { v0 *= LOG2E; v1 *= LOG2E; }
                u32 hh = cvt2bf(v1, v0);
                hb[q] = hh;
                lb[q] = cvt2bf(v1 - bfhi(hh), v0 - bflo(hh));
            }
            u16* dst = (p == 0 ? g_thQ : g_phK) + (size_t)(bg * Nn + n0 + tid) * 32;
            uint4* d4 = (uint4*)dst;
            d4[0] = make_uint4(hb[0],hb[1],hb[2],hb[3]);
            d4[1] = make_uint4(hb[4],hb[5],hb[6],hb[7]);
            d4[2] = make_uint4(lb[0],lb[1],lb[2],lb[3]);
            d4[3] = make_uint4(lb[4],lb[5],lb[6],lb[7]);
        }
    } else {
        const float* bias = A.bias[sel][2];
        int half = tid >> 6, np = tid & 63;
        #pragma unroll 4
        for (int rr = 0; rr < 32; ++rr) {
            int j = rr*2 + half;
            int gabs = g0 + (j >> 4), d = j & 15;
            float bv = bias[gabs*CGd + d];
            float v0 = SM.Cd[j*132 + 2*np]     + bv;
            float v1 = SM.Cd[j*132 + 2*np + 1] + bv;
            u32 hh = cvt2bf(v1, v0);
            size_t off = ((size_t)(sb*Gg + gabs)*CGd + d) * Nn + n0 + 2*np;
            *(u32*)(g_vH + off) = hh;
            *(u32*)(g_vL + off) = cvt2bf(v1 - bfhi(hh), v0 - bflo(hh));
        }
    }
}

// ---------------- Kernel 2: bf16 mma flash attention ----------------
// M-tile 64, cp.async double-buffered K/V, P = bf16 (consistent softmax),
// O += PhVh + PhVl; VH row 16 = ones (denominator), 17-23 = 0.
#define OQ    0
#define OBUF  5120
#define BUFSZ 21120          // K 10240 | VH 6528 | VL 4352
#define OK_   0
#define OVH_  10240
#define OVL_  16768
#define SMSZ  (OBUF + 2*BUFSZ)   // 47360 < 48K static limit

__global__ __launch_bounds__(128, 4) void attn_mma_kernel()
{
    __shared__ __align__(16) char SM[SMSZ];

    int tid = threadIdx.x, lane = tid & 31, wid = tid >> 5;
    int g = blockIdx.y, sbz = blockIdx.z;
    int bg = sbz * Gg + g;
    int n0 = blockIdx.x * 64;

    const u16* thq = g_thQ + (size_t)bg * Nn * 32;
    const u16* phk = g_phK + (size_t)bg * Nn * 32;
    const u16* vh  = g_vH + (size_t)bg * CGd * Nn;
    const u16* vl  = g_vL + (size_t)bg * CGd * Nn;

    u32 SMB = smem_u32(SM);
    u32 QB  = SMB + OQ;

    // Q fill: 64 rows
    if (tid < 64) {
        const uint4* src = (const uint4*)(thq + (size_t)(n0 + tid) * 32);
        uint4* dst = (uint4*)((u16*)(SM + OQ) + tid * 40);
        dst[0] = src[0]; dst[1] = src[1]; dst[2] = src[2]; dst[3] = src[3];
    }
    // VH constant rows 16..23 in BOTH buffers (row 16 = ones)
    #pragma unroll
    for (int b = 0; b < 2; ++b) {
        u16* VHs = (u16*)(SM + OBUF + b * BUFSZ + OVH_);
        #pragma unroll
        for (int i = 0; i < 8; ++i) {
            int r = 16 + i;
            VHs[r * 136 + tid] = (r == 16) ? (u16)0x3F80 : (u16)0;
        }
    }

    int fd = tid >> 3, fblk = (tid & 7) * 16;   // V-fill coords

    // prologue: fill tile 0 into buffer 0
    {
        u32 base = SMB + OBUF;
        const u16* ks = phk + (size_t)tid * 32;
        u32 kd = base + OK_ + (u32)tid * 80;
        cpa16(kd, ks); cpa16(kd + 16, ks + 8);
        cpa16(kd + 32, ks + 16); cpa16(kd + 48, ks + 24);
        const u16* vhs = vh + (size_t)fd * Nn + fblk;
        const u16* vls = vl + (size_t)fd * Nn + fblk;
        u32 vhd = base + OVH_ + (u32)fd * 272 + (u32)fblk * 2;
        u32 vld = base + OVL_ + (u32)fd * 272 + (u32)fblk * 2;
        cpa16(vhd, vhs); cpa16(vhd + 16, vhs + 8);
        cpa16(vld, vls); cpa16(vld + 16, vls + 8);
        CPA_COMMIT();
    }
    CPA_WAIT0();
    __syncthreads();

    // Q A-fragments
    u32 qh[4], ql[4];
    {
        int ar  = (lane & 7) + ((lane >> 3) & 1) * 8;
        int acb = (lane >> 4) * 16;
        u32 ad = QB + (u32)(wid * 16 + ar) * 80 + acb;
        ldsm4(qh, ad);
        ldsm4(ql, ad + 32);
    }

    float O[3][4];
    #pragma unroll
    for (int nt = 0; nt < 3; ++nt)
        #pragma unroll
        for (int q = 0; q < 4; ++q) O[nt][q] = 0.f;

    int krow = (lane & 7) + ((lane >> 4) & 1) * 8;
    int kcb  = ((lane >> 3) & 1) * 16;
    int vrow = (lane & 7);
    int vcb  = ((lane >> 3) & 1) * 16;

    for (int t = 0; t < 18; ++t) {
        u32 cur = SMB + OBUF + (u32)(t & 1) * BUFSZ;

        // prefetch tile t+1 into the other buffer
        if (t < 17) {
            u32 base = SMB + OBUF + (u32)((t + 1) & 1) * BUFSZ;
            int t0n = (t + 1) * 128;
            const u16* ks = phk + (size_t)(t0n + tid) * 32;
            u32 kd = base + OK_ + (u32)tid * 80;
            cpa16(kd, ks); cpa16(kd + 16, ks + 8);
            cpa16(kd + 32, ks + 16); cpa16(kd + 48, ks + 24);
            const u16* vhs = vh + (size_t)fd * Nn + t0n + fblk;
            const u16* vls = vl + (size_t)fd * Nn + t0n + fblk;
            u32 vhd = base + OVH_ + (u32)fd * 272 + (u32)fblk * 2;
            u32 vld = base + OVL_ + (u32)fd * 272 + (u32)fblk * 2;
            cpa16(vhd, vhs); cpa16(vhd + 16, vhs + 8);
            cpa16(vld, vls); cpa16(vld + 16, vls + 8);
            CPA_COMMIT();
        }

        u32 KB = cur + OK_, VHB = cur + OVH_, VLB = cur + OVL_;

        #pragma unroll 2
        for (int c = 0; c < 8; ++c) {
            u32 khb4[4], klb4[4];
            {
                u32 a = KB + (u32)(c * 16 + krow) * 80 + kcb;
                ldsm4(khb4, a);
                ldsm4(klb4, a + 32);
            }
            float C[2][4];
            #pragma unroll
            for (int s = 0; s < 2; ++s) {
                C[s][0] = 0.f; C[s][1] = 0.f; C[s][2] = 0.f; C[s][3] = 0.f;
                mma_bf16(C[s], qh, khb4 + 2*s);
                mma_bf16(C[s], qh, klb4 + 2*s);
                mma_bf16(C[s], ql, khb4 + 2*s);
            }
            u32 pha[4];
            #pragma unroll
            for (int s = 0; s < 2; ++s) {
                float p0 = exp2f_fast(C[s][0]);
                float p1 = exp2f_fast(C[s][1]);
                float p2 = exp2f_fast(C[s][2]);
                float p3 = exp2f_fast(C[s][3]);
                pha[2*s]     = cvt2bf(p1, p0);
                pha[2*s + 1] = cvt2bf(p3, p2);
            }
            u32 vhbf[3][2], vlbf[2][2];
            {
                u32 vbase = (u32)vrow * 272 + (u32)vcb + (u32)c * 32;
                #pragma unroll
                for (int nt = 0; nt < 3; ++nt)
                    ldsm2(vhbf[nt], VHB + vbase + (u32)nt * 8 * 272);
                #pragma unroll
                for (int nt = 0; nt < 2; ++nt)
                    ldsm2(vlbf[nt], VLB + vbase + (u32)nt * 8 * 272);
            }
            #pragma unroll
            for (int nt = 0; nt < 3; ++nt)
                mma_bf16(O[nt], pha, vhbf[nt]);
            #pragma unroll
            for (int nt = 0; nt < 2; ++nt)
                mma_bf16(O[nt], pha, vlbf[nt]);
        }

        if (t < 17) CPA_WAIT0();
        __syncthreads();
    }

    // Epilogue
    float* Es = (float*)(SM + OBUF);
    {
        int gq = lane >> 2, tg = lane & 3;
        #pragma unroll
        for (int nt = 0; nt < 3; ++nt) {
            int r = wid * 16 + gq;
            int col = nt * 8 + 2 * tg;
            Es[r * 26 + col]           = O[nt][0];
            Es[r * 26 + col + 1]       = O[nt][1];
            Es[(r + 8) * 26 + col]     = O[nt][2];
            Es[(r + 8) * 26 + col + 1] = O[nt][3];
        }
    }
    __syncthreads();
    if (tid < 64) {
        float inv = 1.0f / Es[tid * 26 + 16];
        u32 hb[8], lb[8];
        #pragma unroll
        for (int q = 0; q < 8; ++q) {
            float v0 = Es[tid * 26 + 2*q]     * inv;
            float v1 = Es[tid * 26 + 2*q + 1] * inv;
            u32 hh = cvt2bf(v1, v0);
            hb[q] = hh;
            lb[q] = cvt2bf(v1 - bfhi(hh), v0 - bflo(hh));
        }
        size_t off = ((size_t)sbz * Nn + n0 + tid) * INTER + g * CGd;
        uint4* dh = (uint4*)(g_ocTh + off);
        uint4* dl = (uint4*)(g_ocTl + off);
        dh[0] = make_uint4(hb[0],hb[1],hb[2],hb[3]);
        dh[1] = make_uint4(hb[4],hb[5],hb[6],hb[7]);
        dl[0] = make_uint4(lb[0],lb[1],lb[2],lb[3]);
        dl[1] = make_uint4(lb[4],lb[5],lb[6],lb[7]);
    }
}

// ---------------- Kernel 3: W conv via bf16 mma (n-tile 128) ----------------
struct WcArgs { const float* Ww[2]; const float* Wb[2]; };

__global__ __launch_bounds__(128) void wconvmma_kernel(WcArgs A)
{
    // grid (18, 4, 4)
    __shared__ __align__(16) struct {
        u16 Ah[64*40], Al[64*40];
        u16 Bh[128*40], Bl[128*40];
    } SM;

    int tid = threadIdx.x, lane = tid & 31, wid = tid >> 5;
    int n0 = blockIdx.x * 128;
    int o0 = blockIdx.y * 64;
    int sb = blockIdx.z, sel = sb >> 1;

    const float* Ww = A.Ww[sel];
    const u16* och = g_ocTh + (size_t)sb * Nn * INTER;
    const u16* ocl = g_ocTl + (size_t)sb * Nn * INTER;

    float C[16][4];
    #pragma unroll
    for (int i = 0; i < 16; ++i)
        #pragma unroll
        for (int q = 0; q < 4; ++q) C[i][q] = 0.f;

    u32 AhB = smem_u32(SM.Ah), AlB = smem_u32(SM.Al);
    u32 BhB = smem_u32(SM.Bh), BlB = smem_u32(SM.Bl);

    int ar  = (lane & 7) + ((lane >> 3) & 1) * 8;
    int acb = (lane >> 4) * 16;
    int brow = (lane & 7) + ((lane >> 4) & 1) * 8;
    int bcb  = ((lane >> 3) & 1) * 16;

    for (int c0 = 0; c0 < INTER; c0 += 32) {
        {
            int j = tid >> 1, kh2 = (tid & 1) * 16;
            const float* wr = Ww + (size_t)(o0 + j) * INTER + c0 + kh2;
            u32 hb[8], lb[8];
            #pragma unroll
            for (int q = 0; q < 8; ++q) {
                float v0 = wr[2*q], v1 = wr[2*q + 1];
                u32 hh = cvt2bf(v1, v0);
                hb[q] = hh;
                lb[q] = cvt2bf(v1 - bfhi(hh), v0 - bflo(hh));
            }
            uint4* dh = (uint4*)(SM.Ah + j * 40 + kh2);
            uint4* dl = (uint4*)(SM.Al + j * 40 + kh2);
            dh[0] = make_uint4(hb[0],hb[1],hb[2],hb[3]);
            dh[1] = make_uint4(hb[4],hb[5],hb[6],hb[7]);
            dl[0] = make_uint4(lb[0],lb[1],lb[2],lb[3]);
            dl[1] = make_uint4(lb[4],lb[5],lb[6],lb[7]);
        }
        {
            size_t off = (size_t)(n0 + tid) * INTER + c0;
            const uint4* sh = (const uint4*)(och + off);
            const uint4* sl = (const uint4*)(ocl + off);
            uint4* dh = (uint4*)(SM.Bh + tid * 40);
            uint4* dl = (uint4*)(SM.Bl + tid * 40);
            dh[0]=sh[0]; dh[1]=sh[1]; dh[2]=sh[2]; dh[3]=sh[3];
            dl[0]=sl[0]; dl[1]=sl[1]; dl[2]=sl[2]; dl[3]=sl[3];
        }
        __syncthreads();

        #pragma unroll
        for (int kk = 0; kk < 2; ++kk) {
            u32 ah[4], al[4];
            u32 aoff = (u32)(wid*16 + ar) * 80 + kk*32 + acb;
            ldsm4(ah, AhB + aoff);
            ldsm4(al, AlB + aoff);
            #pragma unroll
            for (int nn = 0; nn < 8; ++nn) {
                u32 bh[4], bl[4];
                u32 boff = (u32)(nn*16 + brow) * 80 + kk*32 + bcb;
                ldsm4(bh, BhB + boff);
                ldsm4(bl, BlB + boff);
                mma_bf16(C[2*nn],   ah, bh);
                mma_bf16(C[2*nn],   al, bh);
                mma_bf16(C[2*nn],   ah, bl);
                mma_bf16(C[2*nn+1], ah, bh+2);
                mma_bf16(C[2*nn+1], al, bh+2);
                mma_bf16(C[2*nn+1], ah, bl+2);
            }
        }
        __syncthreads();
    }

    {
        const float* Wb = A.Wb[sel];
        int gq = lane >> 2, tg = lane & 3;
        int o_r = o0 + wid*16 + gq;
        float b0 = Wb[o_r], b1 = Wb[o_r + 8];
        #pragma unroll
        for (int nf = 0; nf < 16; ++nf) {
            int n_c = n0 + nf*8 + 2*tg;
            *(float2*)&g_wy[((size_t)sb*Cc + o_r) * Nn + n_c] =
                make_float2(C[nf][0] + b0, C[nf][1] + b0);
            *(float2*)&g_wy[((size_t)sb*Cc + o_r + 8) * Nn + n_c] =
                make_float2(C[nf][2] + b1, C[nf][3] + b1);
        }
    }
}

// ---------------- Kernel 4: BN stats ----------------
__global__ __launch_bounds__(256) void stats_kernel()
{
    int sel = blockIdx.x / Cc;
    int o   = blockIdx.x % Cc;
    int tid = threadIdx.x;
    const float4* r0 = (const float4*)(g_wy + ((size_t)(sel*Bb + 0) * Cc + o) * Nn);
    const float4* r1 = (const float4*)(g_wy + ((size_t)(sel*Bb + 1) * Cc + o) * Nn);

    float s = 0.f, s2 = 0.f;
    for (int i = tid; i < Nn/4; i += 256) {
        float4 a = r0[i], c = r1[i];
        s += a.x + a.y + a.z + a.w;
        s += c.x + c.y + c.z + c.w;
        s2 = fmaf(a.x, a.x, s2); s2 = fmaf(a.y, a.y, s2);
        s2 = fmaf(a.z, a.z, s2); s2 = fmaf(a.w, a.w, s2);
        s2 = fmaf(c.x, c.x, s2); s2 = fmaf(c.y, c.y, s2);
        s2 = fmaf(c.z, c.z, s2); s2 = fmaf(c.w, c.w, s2);
    }
    __shared__ float sh[256], sh2[256];
    sh[tid] = s; sh2[tid] = s2;
    __syncthreads();
    for (int st = 128; st > 0; st >>= 1) {
        if (tid < st) { sh[tid] += sh[tid + st]; sh2[tid] += sh2[tid + st]; }
        __syncthreads();
    }
    if (tid == 0) {
        float mean = sh[0] * (1.0f / (Bb * Nn));
        float var  = sh2[0] * (1.0f / (Bb * Nn)) - mean * mean;
        g_mean[blockIdx.x] = mean;
        g_rstd[blockIdx.x] = rsqrtf(var + EPSf);
    }
}

// ---------------- Kernel 5: BN apply + residual + ReLU ----------------
struct ApplyArgs {
    const float* x[2];
    const float* gam[2]; const float* bet[2];
};

__global__ __launch_bounds__(256) void apply_kernel(ApplyArgs A, float* __restrict__ out)
{
    int i4 = blockIdx.x * 256 + threadIdx.x;
    int idx = i4 * 4;
    int per = Bb * Cc * Nn;
    int sel = idx / per;
    int loc = idx - sel * per;
    int o   = (loc / Nn) % Cc;
    float m  = g_mean[sel*Cc + o];
    float rs = g_rstd[sel*Cc + o];
    float ga = A.gam[sel][o], be = A.bet[sel][o];
    float4 wv = *(const float4*)(g_wy + idx);
    float4 xv = *(const float4*)(A.x[sel] + loc);
    float4 r;
    r.x = fmaxf(fmaf((wv.x - m) * rs, ga, be) + xv.x, 0.f);
    r.y = fmaxf(fmaf((wv.y - m) * rs, ga, be) + xv.y, 0.f);
    r.z = fmaxf(fmaf((wv.z - m) * rs, ga, be) + xv.z, 0.f);
    r.w = fmaxf(fmaf((wv.w - m) * rs, ga, be) + xv.w, 0.f);
    *(float4*)(out + idx) = r;
}

// ---------------- launch ----------------
extern "C" void kernel_launch(void* const* d_in, const int* in_sizes, int n_in,
                              void* d_out, int out_size)
{
    XArgs X; PjArgs P; WcArgs W; ApplyArgs AP;
    for (int s = 0; s < 2; ++s) {
        X.x[s] = (const float*)d_in[s];
        P.w[s][0]    = (const float*)d_in[2 + s*10 + 2];
        P.bias[s][0] = (const float*)d_in[2 + s*10 + 3];
        P.w[s][1]    = (const float*)d_in[2 + s*10 + 4];
        P.bias[s][1] = (const float*)d_in[2 + s*10 + 5];
        P.w[s][2]    = (const float*)d_in[2 + s*10 + 0];
        P.bias[s][2] = (const float*)d_in[2 + s*10 + 1];
        W.Ww[s] = (const float*)d_in[2 + s*10 + 6];
        W.Wb[s] = (const float*)d_in[2 + s*10 + 7];
        AP.x[s]   = (const float*)d_in[s];
        AP.gam[s] = (const float*)d_in[2 + s*10 + 8];
        AP.bet[s] = (const float*)d_in[2 + s*10 + 9];
    }

    xcvt_kernel    <<<dim3(18, 4), 256>>>(X);
    projmma_kernel <<<dim3(18, 6, 4), 128>>>(P);
    attn_mma_kernel<<<dim3(36, Gg, SEL*Bb), 128>>>();
    wconvmma_kernel<<<dim3(18, 4, 4), 128>>>(W);
    stats_kernel   <<<SEL*Cc, 256>>>();
    apply_kernel   <<<(SEL*Bb*Cc*Nn)/1024, 256>>>(AP, (float*)d_out);
}

// round 15
// speedup vs baseline: 1.0888x; 1.0504x over previous
#include <cuda_runtime.h>
#include <cstdint>

typedef unsigned int u32;
typedef unsigned short u16;

#define SEL   2
#define Bb    2
#define Cc    256
#define Nn    2304
#define Gg    8
#define CGd   16
#define INTER 128
#define EPSf  1e-5f
#define LOG2E 1.4426950408889634f
#define SHIFT 16.0f
#define CLMP  14.0f

// ---------------- scratch ----------------
__device__ __align__(16) u16  g_xTh[SEL*Bb*Nn*Cc];     // fp16 hi
__device__ __align__(16) u16  g_xTl[SEL*Bb*Nn*Cc];     // fp16 lo
__device__ __align__(16) u16  g_thQ[SEL*Bb*Gg*Nn*32];  // [bg][n][16h|16l] theta*log2e
__device__ __align__(16) u16  g_phK[SEL*Bb*Gg*Nn*32];
__device__ __align__(16) u16  g_vH [SEL*Bb*Gg*CGd*Nn];
__device__ __align__(16) u16  g_vL [SEL*Bb*Gg*CGd*Nn];
__device__ __align__(16) u16  g_ocTh[SEL*Bb*Nn*INTER];
__device__ __align__(16) u16  g_ocTl[SEL*Bb*Nn*INTER];
__device__ float g_wy  [SEL*Bb*Cc*Nn];
__device__ float g_mean[SEL*Cc];
__device__ float g_rstd[SEL*Cc];

// ---------------- helpers ----------------
__device__ __forceinline__ u32 smem_u32(const void* p) {
    u32 a;
    asm("{ .reg .u64 t; cvta.to.shared.u64 t, %1; cvt.u32.u64 %0, t; }" : "=r"(a) : "l"(p));
    return a;
}
__device__ __forceinline__ u32 cvt2h(float hi, float lo) {
    u32 d; asm("cvt.rn.f16x2.f32 %0, %1, %2;" : "=r"(d) : "f"(hi), "f"(lo)); return d;
}
__device__ __forceinline__ float hlo(u32 w) {
    float f; asm("{.reg .b16 a,b; mov.b32 {a,b}, %1; cvt.f32.f16 %0, a;}" : "=f"(f) : "r"(w)); return f;
}
__device__ __forceinline__ float hhi(u32 w) {
    float f; asm("{.reg .b16 a,b; mov.b32 {a,b}, %1; cvt.f32.f16 %0, b;}" : "=f"(f) : "r"(w)); return f;
}
__device__ __forceinline__ void ldsm4(u32* r, u32 a) {
    asm volatile("ldmatrix.sync.aligned.m8n8.x4.shared.b16 {%0,%1,%2,%3}, [%4];"
        : "=r"(r[0]), "=r"(r[1]), "=r"(r[2]), "=r"(r[3]) : "r"(a));
}
__device__ __forceinline__ void ldsm2(u32* r, u32 a) {
    asm volatile("ldmatrix.sync.aligned.m8n8.x2.shared.b16 {%0,%1}, [%2];"
        : "=r"(r[0]), "=r"(r[1]) : "r"(a));
}
__device__ __forceinline__ void mma_f16(float* c, const u32* a, const u32* b) {
    asm volatile("mma.sync.aligned.m16n8k16.row.col.f32.f16.f16.f32 "
        "{%0,%1,%2,%3}, {%4,%5,%6,%7}, {%8,%9}, {%0,%1,%2,%3};"
        : "+f"(c[0]), "+f"(c[1]), "+f"(c[2]), "+f"(c[3])
        : "r"(a[0]), "r"(a[1]), "r"(a[2]), "r"(a[3]), "r"(b[0]), "r"(b[1]));
}
__device__ __forceinline__ void cpa16(u32 dst, const void* src) {
    asm volatile("cp.async.cg.shared.global [%0], [%1], 16;" :: "r"(dst), "l"(src));
}
#define CPA_COMMIT() asm volatile("cp.async.commit_group;" ::: "memory")
#define CPA_WAIT0()  asm volatile("cp.async.wait_group 0;" ::: "memory")

__device__ __forceinline__ float ex2f(float t) {
    float r; asm("ex2.approx.f32 %0, %1;" : "=f"(r) : "f"(t)); return r;
}
// exp2(min(t - SHIFT, CLMP)) — fp16-overflow-proof
__device__ __forceinline__ float ex2s(float t) {
    return ex2f(fminf(t - SHIFT, CLMP));
}

// ---------------- Kernel 0: x -> transposed fp16 hi/lo [sb][n][c] ----------------
struct XArgs { const float* x[2]; };

__global__ __launch_bounds__(256) void xcvt_kernel(XArgs A)
{
    int n0 = blockIdx.x * 128;
    int sb = blockIdx.y;
    int sel = sb >> 1, b = sb & 1;
    const float* x = A.x[sel] + (size_t)b * Cc * Nn;
    __shared__ float T[64][132];
    int tid = threadIdx.x;

    for (int c0 = 0; c0 < Cc; c0 += 64) {
        int nn = tid & 127, ch = tid >> 7;
        #pragma unroll 8
        for (int i = 0; i < 32; ++i)
            T[ch + 2*i][nn] = x[(size_t)(c0 + ch + 2*i) * Nn + n0 + nn];
        __syncthreads();
        int n = tid >> 1, kh = (tid & 1) * 32;
        u32 hb[16], lb[16];
        #pragma unroll
        for (int j = 0; j < 16; ++j) {
            float v0 = T[kh + 2*j][n], v1 = T[kh + 2*j + 1][n];
            u32 hh = cvt2h(v1, v0);
            hb[j] = hh;
            lb[j] = cvt2h(v1 - hhi(hh), v0 - hlo(hh));
        }
        size_t off = ((size_t)sb * Nn + n0 + n) * Cc + c0 + kh;
        uint4* dh = (uint4*)(g_xTh + off);
        uint4* dl = (uint4*)(g_xTl + off);
        dh[0] = make_uint4(hb[0],hb[1],hb[2],hb[3]);
        dh[1] = make_uint4(hb[4],hb[5],hb[6],hb[7]);
        dh[2] = make_uint4(hb[8],hb[9],hb[10],hb[11]);
        dh[3] = make_uint4(hb[12],hb[13],hb[14],hb[15]);
        dl[0] = make_uint4(lb[0],lb[1],lb[2],lb[3]);
        dl[1] = make_uint4(lb[4],lb[5],lb[6],lb[7]);
        dl[2] = make_uint4(lb[8],lb[9],lb[10],lb[11]);
        dl[3] = make_uint4(lb[12],lb[13],lb[14],lb[15]);
        __syncthreads();
    }
}

// ---------------- Kernel 1: grouped projections via fp16 mma ----------------
struct PjArgs {
    const float* w[2][3];
    const float* bias[2][3];
};

__global__ __launch_bounds__(128) void projmma_kernel(PjArgs A)
{
    __shared__ __align__(16) union {
        struct {
            u16 Ah[64*40], Al[64*40];
            u16 Bh[128*40], Bl[128*40];
        } m;
        float Cd[64*132];
    } SM;

    int tid = threadIdx.x, lane = tid & 31, wid = tid >> 5;
    int n0 = blockIdx.x * 128;
    int jt = blockIdx.y;
    int sb = blockIdx.z, sel = sb >> 1;
    int p  = jt >> 1;
    int g0 = (jt & 1) * 4;

    const float* wsrc = A.w[sel][p] + (size_t)(g0 * CGd) * Cc;
    const u16* xh = g_xTh + (size_t)sb * Nn * Cc;
    const u16* xl = g_xTl + (size_t)sb * Nn * Cc;

    float C[16][4];
    #pragma unroll
    for (int i = 0; i < 16; ++i)
        #pragma unroll
        for (int q = 0; q < 4; ++q) C[i][q] = 0.f;

    u32 AhB = smem_u32(SM.m.Ah), AlB = smem_u32(SM.m.Al);
    u32 BhB = smem_u32(SM.m.Bh), BlB = smem_u32(SM.m.Bl);

    int ar  = (lane & 7) + ((lane >> 3) & 1) * 8;
    int acb = (lane >> 4) * 16;
    int brow = (lane & 7) + ((lane >> 4) & 1) * 8;
    int bcb  = ((lane >> 3) & 1) * 16;

    for (int c0 = 0; c0 < Cc; c0 += 32) {
        {
            int j = tid >> 1, kh2 = (tid & 1) * 16;
            const float* wr = wsrc + (size_t)j * Cc + c0 + kh2;
            u32 hb[8], lb[8];
            #pragma unroll
            for (int q = 0; q < 8; ++q) {
                float v0 = wr[2*q], v1 = wr[2*q + 1];
                u32 hh = cvt2h(v1, v0);
                hb[q] = hh;
                lb[q] = cvt2h(v1 - hhi(hh), v0 - hlo(hh));
            }
            uint4* dh = (uint4*)(SM.m.Ah + j * 40 + kh2);
            uint4* dl = (uint4*)(SM.m.Al + j * 40 + kh2);
            dh[0] = make_uint4(hb[0],hb[1],hb[2],hb[3]);
            dh[1] = make_uint4(hb[4],hb[5],hb[6],hb[7]);
            dl[0] = make_uint4(lb[0],lb[1],lb[2],lb[3]);
            dl[1] = make_uint4(lb[4],lb[5],lb[6],lb[7]);
        }
        {
            size_t off = (size_t)(n0 + tid) * Cc + c0;
            const uint4* sh = (const uint4*)(xh + off);
            const uint4* sl = (const uint4*)(xl + off);
            uint4* dh = (uint4*)(SM.m.Bh + tid * 40);
            uint4* dl = (uint4*)(SM.m.Bl + tid * 40);
            dh[0]=sh[0]; dh[1]=sh[1]; dh[2]=sh[2]; dh[3]=sh[3];
            dl[0]=sl[0]; dl[1]=sl[1]; dl[2]=sl[2]; dl[3]=sl[3];
        }
        __syncthreads();

        #pragma unroll
        for (int kk = 0; kk < 2; ++kk) {
            u32 ah[4], al[4];
            u32 aoff = (u32)(wid*16 + ar) * 80 + kk*32 + acb;
            ldsm4(ah, AhB + aoff);
            ldsm4(al, AlB + aoff);
            #pragma unroll
            for (int nn = 0; nn < 8; ++nn) {
                u32 bh[4], bl[4];
                u32 boff = (u32)(nn*16 + brow) * 80 + kk*32 + bcb;
                ldsm4(bh, BhB + boff);
                ldsm4(bl, BlB + boff);
                mma_f16(C[2*nn],   ah, bh);
                mma_f16(C[2*nn],   al, bh);
                mma_f16(C[2*nn],   ah, bl);
                mma_f16(C[2*nn+1], ah, bh+2);
                mma_f16(C[2*nn+1], al, bh+2);
                mma_f16(C[2*nn+1], ah, bl+2);
            }
        }
        __syncthreads();
    }

    {
        int gq = lane >> 2, tg = lane & 3;
        #pragma unroll
        for (int nf = 0; nf < 16; ++nf) {
            int r = wid*16 + gq, col = nf*8 + 2*tg;
            *(float2*)&SM.Cd[r*132 + col]       = make_float2(C[nf][0], C[nf][1]);
            *(float2*)&SM.Cd[(r+8)*132 + col]   = make_float2(C[nf][2], C[nf][3]);
        }
    }
    __syncthreads();

    if (p < 2) {
        const float* bias = A.bias[sel][p];
        #pragma unroll
        for (int gg = 0; gg < 4; ++gg) {
            int gabs = g0 + gg;
            int bg = sb * Gg + gabs;
            u32 hb[8], lb[8];
            #pragma unroll
            for (int q = 0; q < 8; ++q) {
                float v0 = SM.Cd[(gg*16 + 2*q)*132 + tid]   + bias[gabs*CGd + 2*q];
                float v1 = SM.Cd[(gg*16 + 2*q+1)*132 + tid] + bias[gabs*CGd + 2*q + 1];
                if (p == 0) { v0 *= LOG2E; v1 *= LOG2E; }
                u32 hh = cvt2h(v1, v0);
                hb[q] = hh;
                lb[q] = cvt2h(v1 - hhi(hh), v0 - hlo(hh));
            }
            u16* dst = (p == 0 ? g_thQ : g_phK) + (size_t)(bg * Nn + n0 + tid) * 32;
            uint4* d4 = (uint4*)dst;
            d4[0] = make_uint4(hb[0],hb[1],hb[2],hb[3]);
            d4[1] = make_uint4(hb[4],hb[5],hb[6],hb[7]);
            d4[2] = make_uint4(lb[0],lb[1],lb[2],lb[3]);
            d4[3] = make_uint4(lb[4],lb[5],lb[6],lb[7]);
        }
    } else {
        const float* bias = A.bias[sel][2];
        int half = tid >> 6, np = tid & 63;
        #pragma unroll 4
        for (int rr = 0; rr < 32; ++rr) {
            int j = rr*2 + half;
            int gabs = g0 + (j >> 4), d = j & 15;
            float bv = bias[gabs*CGd + d];
            float v0 = SM.Cd[j*132 + 2*np]     + bv;
            float v1 = SM.Cd[j*132 + 2*np + 1] + bv;
            u32 hh = cvt2h(v1, v0);
            size_t off = ((size_t)(sb*Gg + gabs)*CGd + d) * Nn + n0 + 2*np;
            *(u32*)(g_vH + off) = hh;
            *(u32*)(g_vL + off) = cvt2h(v1 - hhi(hh), v0 - hlo(hh));
        }
    }
}

// ---------------- Kernel 2: fp16 mma flash attention ----------------
// M-tile 64, cp.async double-buffered K/V; P = fp16(ex2(min(S-16,14))):
// overflow-proof, shift cancels in ones-column-normalized softmax.
#define OQ    0
#define OBUF  5120
#define BUFSZ 21120
#define OK_   0
#define OVH_  10240
#define OVL_  16768
#define SMSZ  (OBUF + 2*BUFSZ)

__global__ __launch_bounds__(128, 4) void attn_mma_kernel()
{
    __shared__ __align__(16) char SM[SMSZ];

    int tid = threadIdx.x, lane = tid & 31, wid = tid >> 5;
    int g = blockIdx.y, sbz = blockIdx.z;
    int bg = sbz * Gg + g;
    int n0 = blockIdx.x * 64;

    const u16* thq = g_thQ + (size_t)bg * Nn * 32;
    const u16* phk = g_phK + (size_t)bg * Nn * 32;
    const u16* vh  = g_vH + (size_t)bg * CGd * Nn;
    const u16* vl  = g_vL + (size_t)bg * CGd * Nn;

    u32 SMB = smem_u32(SM);
    u32 QB  = SMB + OQ;

    if (tid < 64) {
        const uint4* src = (const uint4*)(thq + (size_t)(n0 + tid) * 32);
        uint4* dst = (uint4*)((u16*)(SM + OQ) + tid * 40);
        dst[0] = src[0]; dst[1] = src[1]; dst[2] = src[2]; dst[3] = src[3];
    }
    #pragma unroll
    for (int b = 0; b < 2; ++b) {
        u16* VHs = (u16*)(SM + OBUF + b * BUFSZ + OVH_);
        #pragma unroll
        for (int i = 0; i < 8; ++i) {
            int r = 16 + i;
            VHs[r * 136 + tid] = (r == 16) ? (u16)0x3C00 : (u16)0;   // fp16 1.0
        }
    }

    int fd = tid >> 3, fblk = (tid & 7) * 16;

    {
        u32 base = SMB + OBUF;
        const u16* ks = phk + (size_t)tid * 32;
        u32 kd = base + OK_ + (u32)tid * 80;
        cpa16(kd, ks); cpa16(kd + 16, ks + 8);
        cpa16(kd + 32, ks + 16); cpa16(kd + 48, ks + 24);
        const u16* vhs = vh + (size_t)fd * Nn + fblk;
        const u16* vls = vl + (size_t)fd * Nn + fblk;
        u32 vhd = base + OVH_ + (u32)fd * 272 + (u32)fblk * 2;
        u32 vld = base + OVL_ + (u32)fd * 272 + (u32)fblk * 2;
        cpa16(vhd, vhs); cpa16(vhd + 16, vhs + 8);
        cpa16(vld, vls); cpa16(vld + 16, vls + 8);
        CPA_COMMIT();
    }
    CPA_WAIT0();
    __syncthreads();

    u32 qh[4], ql[4];
    {
        int ar  = (lane & 7) + ((lane >> 3) & 1) * 8;
        int acb = (lane >> 4) * 16;
        u32 ad = QB + (u32)(wid * 16 + ar) * 80 + acb;
        ldsm4(qh, ad);
        ldsm4(ql, ad + 32);
    }

    float O[3][4];
    #pragma unroll
    for (int nt = 0; nt < 3; ++nt)
        #pragma unroll
        for (int q = 0; q < 4; ++q) O[nt][q] = 0.f;

    int krow = (lane & 7) + ((lane >> 4) & 1) * 8;
    int kcb  = ((lane >> 3) & 1) * 16;
    int vrow = (lane & 7);
    int vcb  = ((lane >> 3) & 1) * 16;

    for (int t = 0; t < 18; ++t) {
        u32 cur = SMB + OBUF + (u32)(t & 1) * BUFSZ;

        if (t < 17) {
            u32 base = SMB + OBUF + (u32)((t + 1) & 1) * BUFSZ;
            int t0n = (t + 1) * 128;
            const u16* ks = phk + (size_t)(t0n + tid) * 32;
            u32 kd = base + OK_ + (u32)tid * 80;
            cpa16(kd, ks); cpa16(kd + 16, ks + 8);
            cpa16(kd + 32, ks + 16); cpa16(kd + 48, ks + 24);
            const u16* vhs = vh + (size_t)fd * Nn + t0n + fblk;
            const u16* vls = vl + (size_t)fd * Nn + t0n + fblk;
            u32 vhd = base + OVH_ + (u32)fd * 272 + (u32)fblk * 2;
            u32 vld = base + OVL_ + (u32)fd * 272 + (u32)fblk * 2;
            cpa16(vhd, vhs); cpa16(vhd + 16, vhs + 8);
            cpa16(vld, vls); cpa16(vld + 16, vls + 8);
            CPA_COMMIT();
        }

        u32 KB = cur + OK_, VHB = cur + OVH_, VLB = cur + OVL_;

        #pragma unroll 2
        for (int c = 0; c < 8; ++c) {
            u32 khb4[4], klb4[4];
            {
                u32 a = KB + (u32)(c * 16 + krow) * 80 + kcb;
                ldsm4(khb4, a);
                ldsm4(klb4, a + 32);
            }
            float C[2][4];
            #pragma unroll
            for (int s = 0; s < 2; ++s) {
                C[s][0] = 0.f; C[s][1] = 0.f; C[s][2] = 0.f; C[s][3] = 0.f;
                mma_f16(C[s], qh, khb4 + 2*s);
                mma_f16(C[s], qh, klb4 + 2*s);
                mma_f16(C[s], ql, khb4 + 2*s);
            }
            u32 pha[4];
            #pragma unroll
            for (int s = 0; s < 2; ++s) {
                float p0 = ex2s(C[s][0]);
                float p1 = ex2s(C[s][1]);
                float p2 = ex2s(C[s][2]);
                float p3 = ex2s(C[s][3]);
                pha[2*s]     = cvt2h(p1, p0);
                pha[2*s + 1] = cvt2h(p3, p2);
            }
            u32 vhbf[3][2], vlbf[2][2];
            {
                u32 vbase = (u32)vrow * 272 + (u32)vcb + (u32)c * 32;
                #pragma unroll
                for (int nt = 0; nt < 3; ++nt)
                    ldsm2(vhbf[nt], VHB + vbase + (u32)nt * 8 * 272);
                #pragma unroll
                for (int nt = 0; nt < 2; ++nt)
                    ldsm2(vlbf[nt], VLB + vbase + (u32)nt * 8 * 272);
            }
            #pragma unroll
            for (int nt = 0; nt < 3; ++nt)
                mma_f16(O[nt], pha, vhbf[nt]);
            #pragma unroll
            for (int nt = 0; nt < 2; ++nt)
                mma_f16(O[nt], pha, vlbf[nt]);
        }

        if (t < 17) CPA_WAIT0();
        __syncthreads();
    }

    float* Es = (float*)(SM + OBUF);
    {
        int gq = lane >> 2, tg = lane & 3;
        #pragma unroll
        for (int nt = 0; nt < 3; ++nt) {
            int r = wid * 16 + gq;
            int col = nt * 8 + 2 * tg;
            Es[r * 26 + col]           = O[nt][0];
            Es[r * 26 + col + 1]       = O[nt][1];
            Es[(r + 8) * 26 + col]     = O[nt][2];
            Es[(r + 8) * 26 + col + 1] = O[nt][3];
        }
    }
    __syncthreads();
    if (tid < 64) {
        float inv = 1.0f / Es[tid * 26 + 16];
        u32 hb[8], lb[8];
        #pragma unroll
        for (int q = 0; q < 8; ++q) {
            float v0 = Es[tid * 26 + 2*q]     * inv;
            float v1 = Es[tid * 26 + 2*q + 1] * inv;
            u32 hh = cvt2h(v1, v0);
            hb[q] = hh;
            lb[q] = cvt2h(v1 - hhi(hh), v0 - hlo(hh));
        }
        size_t off = ((size_t)sbz * Nn + n0 + tid) * INTER + g * CGd;
        uint4* dh = (uint4*)(g_ocTh + off);
        uint4* dl = (uint4*)(g_ocTl + off);
        dh[0] = make_uint4(hb[0],hb[1],hb[2],hb[3]);
        dh[1] = make_uint4(hb[4],hb[5],hb[6],hb[7]);
        dl[0] = make_uint4(lb[0],lb[1],lb[2],lb[3]);
        dl[1] = make_uint4(lb[4],lb[5],lb[6],lb[7]);
    }
}

// ---------------- Kernel 3: W conv via fp16 mma (n-tile 128) ----------------
struct WcArgs { const float* Ww[2]; const float* Wb[2]; };

__global__ __launch_bounds__(128) void wconvmma_kernel(WcArgs A)
{
    __shared__ __align__(16) struct {
        u16 Ah[64*40], Al[64*40];
        u16 Bh[128*40], Bl[128*40];
    } SM;

    int tid = threadIdx.x, lane = tid & 31, wid = tid >> 5;
    int n0 = blockIdx.x * 128;
    int o0 = blockIdx.y * 64;
    int sb = blockIdx.z, sel = sb >> 1;

    const float* Ww = A.Ww[sel];
    const u16* och = g_ocTh + (size_t)sb * Nn * INTER;
    const u16* ocl = g_ocTl + (size_t)sb * Nn * INTER;

    float C[16][4];
    #pragma unroll
    for (int i = 0; i < 16; ++i)
        #pragma unroll
        for (int q = 0; q < 4; ++q) C[i][q] = 0.f;

    u32 AhB = smem_u32(SM.Ah), AlB = smem_u32(SM.Al);
    u32 BhB = smem_u32(SM.Bh), BlB = smem_u32(SM.Bl);

    int ar  = (lane & 7) + ((lane >> 3) & 1) * 8;
    int acb = (lane >> 4) * 16;
    int brow = (lane & 7) + ((lane >> 4) & 1) * 8;
    int bcb  = ((lane >> 3) & 1) * 16;

    for (int c0 = 0; c0 < INTER; c0 += 32) {
        {
            int j = tid >> 1, kh2 = (tid & 1) * 16;
            const float* wr = Ww + (size_t)(o0 + j) * INTER + c0 + kh2;
            u32 hb[8], lb[8];
            #pragma unroll
            for (int q = 0; q < 8; ++q) {
                float v0 = wr[2*q], v1 = wr[2*q + 1];
                u32 hh = cvt2h(v1, v0);
                hb[q] = hh;
                lb[q] = cvt2h(v1 - hhi(hh), v0 - hlo(hh));
            }
            uint4* dh = (uint4*)(SM.Ah + j * 40 + kh2);
            uint4* dl = (uint4*)(SM.Al + j * 40 + kh2);
            dh[0] = make_uint4(hb[0],hb[1],hb[2],hb[3]);
            dh[1] = make_uint4(hb[4],hb[5],hb[6],hb[7]);
            dl[0] = make_uint4(lb[0],lb[1],lb[2],lb[3]);
            dl[1] = make_uint4(lb[4],lb[5],lb[6],lb[7]);
        }
        {
            size_t off = (size_t)(n0 + tid) * INTER + c0;
            const uint4* sh = (const uint4*)(och + off);
            const uint4* sl = (const uint4*)(ocl + off);
            uint4* dh = (uint4*)(SM.Bh + tid * 40);
            uint4* dl = (uint4*)(SM.Bl + tid * 40);
            dh[0]=sh[0]; dh[1]=sh[1]; dh[2]=sh[2]; dh[3]=sh[3];
            dl[0]=sl[0]; dl[1]=sl[1]; dl[2]=sl[2]; dl[3]=sl[3];
        }
        __syncthreads();

        #pragma unroll
        for (int kk = 0; kk < 2; ++kk) {
            u32 ah[4], al[4];
            u32 aoff = (u32)(wid*16 + ar) * 80 + kk*32 + acb;
            ldsm4(ah, AhB + aoff);
            ldsm4(al, AlB + aoff);
            #pragma unroll
            for (int nn = 0; nn < 8; ++nn) {
                u32 bh[4], bl[4];
                u32 boff = (u32)(nn*16 + brow) * 80 + kk*32 + bcb;
                ldsm4(bh, BhB + boff);
                ldsm4(bl, BlB + boff);
                mma_f16(C[2*nn],   ah, bh);
                mma_f16(C[2*nn],   al, bh);
                mma_f16(C[2*nn],   ah, bl);
                mma_f16(C[2*nn+1], ah, bh+2);
                mma_f16(C[2*nn+1], al, bh+2);
                mma_f16(C[2*nn+1], ah, bl+2);
            }
        }
        __syncthreads();
    }

    {
        const float* Wb = A.Wb[sel];
        int gq = lane >> 2, tg = lane & 3;
        int o_r = o0 + wid*16 + gq;
        float b0 = Wb[o_r], b1 = Wb[o_r + 8];
        #pragma unroll
        for (int nf = 0; nf < 16; ++nf) {
            int n_c = n0 + nf*8 + 2*tg;
            *(float2*)&g_wy[((size_t)sb*Cc + o_r) * Nn + n_c] =
                make_float2(C[nf][0] + b0, C[nf][1] + b0);
            *(float2*)&g_wy[((size_t)sb*Cc + o_r + 8) * Nn + n_c] =
                make_float2(C[nf][2] + b1, C[nf][3] + b1);
        }
    }
}

// ---------------- Kernel 4: BN stats ----------------
__global__ __launch_bounds__(256) void stats_kernel()
{
    int sel = blockIdx.x / Cc;
    int o   = blockIdx.x % Cc;
    int tid = threadIdx.x;
    const float4* r0 = (const float4*)(g_wy + ((size_t)(sel*Bb + 0) * Cc + o) * Nn);
    const float4* r1 = (const float4*)(g_wy + ((size_t)(sel*Bb + 1) * Cc + o) * Nn);

    float s = 0.f, s2 = 0.f;
    for (int i = tid; i < Nn/4; i += 256) {
        float4 a = r0[i], c = r1[i];
        s += a.x + a.y + a.z + a.w;
        s += c.x + c.y + c.z + c.w;
        s2 = fmaf(a.x, a.x, s2); s2 = fmaf(a.y, a.y, s2);
        s2 = fmaf(a.z, a.z, s2); s2 = fmaf(a.w, a.w, s2);
        s2 = fmaf(c.x, c.x, s2); s2 = fmaf(c.y, c.y, s2);
        s2 = fmaf(c.z, c.z, s2); s2 = fmaf(c.w, c.w, s2);
    }
    __shared__ float sh[256], sh2[256];
    sh[tid] = s; sh2[tid] = s2;
    __syncthreads();
    for (int st = 128; st > 0; st >>= 1) {
        if (tid < st) { sh[tid] += sh[tid + st]; sh2[tid] += sh2[tid + st]; }
        __syncthreads();
    }
    if (tid == 0) {
        float mean = sh[0] * (1.0f / (Bb * Nn));
        float var  = sh2[0] * (1.0f / (Bb * Nn)) - mean * mean;
        g_mean[blockIdx.x] = mean;
        g_rstd[blockIdx.x] = rsqrtf(var + EPSf);
    }
}

// ---------------- Kernel 5: BN apply + residual + ReLU ----------------
struct ApplyArgs {
    const float* x[2];
    const float* gam[2]; const float* bet[2];
};

__global__ __launch_bounds__(256) void apply_kernel(ApplyArgs A, float* __restrict__ out)
{
    int i4 = blockIdx.x * 256 + threadIdx.x;
    int idx = i4 * 4;
    int per = Bb * Cc * Nn;
    int sel = idx / per;
    int loc = idx - sel * per;
    int o   = (loc / Nn) % Cc;
    float m  = g_mean[sel*Cc + o];
    float rs = g_rstd[sel*Cc + o];
    float ga = A.gam[sel][o], be = A.bet[sel][o];
    float4 wv = *(const float4*)(g_wy + idx);
    float4 xv = *(const float4*)(A.x[sel] + loc);
    float4 r;
    r.x = fmaxf(fmaf((wv.x - m) * rs, ga, be) + xv.x, 0.f);
    r.y = fmaxf(fmaf((wv.y - m) * rs, ga, be) + xv.y, 0.f);
    r.z = fmaxf(fmaf((wv.z - m) * rs, ga, be) + xv.z, 0.f);
    r.w = fmaxf(fmaf((wv.w - m) * rs, ga, be) + xv.w, 0.f);
    *(float4*)(out + idx) = r;
}

// ---------------- launch ----------------
extern "C" void kernel_launch(void* const* d_in, const int* in_sizes, int n_in,
                              void* d_out, int out_size)
{
    XArgs X; PjArgs P; WcArgs W; ApplyArgs AP;
    for (int s = 0; s < 2; ++s) {
        X.x[s] = (const float*)d_in[s];
        P.w[s][0]    = (const float*)d_in[2 + s*10 + 2];
        P.bias[s][0] = (const float*)d_in[2 + s*10 + 3];
        P.w[s][1]    = (const float*)d_in[2 + s*10 + 4];
        P.bias[s][1] = (const float*)d_in[2 + s*10 + 5];
        P.w[s][2]    = (const float*)d_in[2 + s*10 + 0];
        P.bias[s][2] = (const float*)d_in[2 + s*10 + 1];
        W.Ww[s] = (const float*)d_in[2 + s*10 + 6];
        W.Wb[s] = (const float*)d_in[2 + s*10 + 7];
        AP.x[s]   = (const float*)d_in[s];
        AP.gam[s] = (const float*)d_in[2 + s*10 + 8];
        AP.bet[s] = (const float*)d_in[2 + s*10 + 9];
    }

    xcvt_kernel    <<<dim3(18, 4), 256>>>(X);
    projmma_kernel <<<dim3(18, 6, 4), 128>>>(P);
    attn_mma_kernel<<<dim3(36, Gg, SEL*Bb), 128>>>();
    wconvmma_kernel<<<dim3(18, 4, 4), 128>>>(W);
    stats_kernel   <<<SEL*Cc, 256>>>();
    apply_kernel   <<<(SEL*Bb*Cc*Nn)/1024, 256>>>(AP, (float*)d_out);
}

// round 16
// speedup vs baseline: 1.2502x; 1.1482x over previous
#include <cuda_runtime.h>
#include <cstdint>

typedef unsigned int u32;
typedef unsigned short u16;

#define SEL   2
#define Bb    2
#define Cc    256
#define Nn    2304
#define Gg    8
#define CGd   16
#define INTER 128
#define EPSf  1e-5f
#define LOG2E 1.4426950408889634f
#define SHIFT 16.0f
#define CLMP  14.0f

// ---------------- scratch ----------------
__device__ __align__(16) u16  g_xTh[SEL*Bb*Nn*Cc];     // fp16 hi
__device__ __align__(16) u16  g_xTl[SEL*Bb*Nn*Cc];     // fp16 lo
__device__ __align__(16) u16  g_thQ[SEL*Bb*Gg*Nn*32];  // [bg][n][16h|16l] theta*log2e
__device__ __align__(16) u16  g_phK[SEL*Bb*Gg*Nn*32];
__device__ __align__(16) u16  g_vH [SEL*Bb*Gg*CGd*Nn];
__device__ __align__(16) u16  g_vL [SEL*Bb*Gg*CGd*Nn];
__device__ __align__(16) u16  g_ocTh[SEL*Bb*Nn*INTER];
__device__ __align__(16) u16  g_ocTl[SEL*Bb*Nn*INTER];
__device__ float g_wy  [SEL*Bb*Cc*Nn];
__device__ float g_mean[SEL*Cc];
__device__ float g_rstd[SEL*Cc];

// ---------------- helpers ----------------
__device__ __forceinline__ u32 smem_u32(const void* p) {
    u32 a;
    asm("{ .reg .u64 t; cvta.to.shared.u64 t, %1; cvt.u32.u64 %0, t; }" : "=r"(a) : "l"(p));
    return a;
}
__device__ __forceinline__ u32 cvt2h(float hi, float lo) {
    u32 d; asm("cvt.rn.f16x2.f32 %0, %1, %2;" : "=r"(d) : "f"(hi), "f"(lo)); return d;
}
__device__ __forceinline__ float hlo(u32 w) {
    float f; asm("{.reg .b16 a,b; mov.b32 {a,b}, %1; cvt.f32.f16 %0, a;}" : "=f"(f) : "r"(w)); return f;
}
__device__ __forceinline__ float hhi(u32 w) {
    float f; asm("{.reg .b16 a,b; mov.b32 {a,b}, %1; cvt.f32.f16 %0, b;}" : "=f"(f) : "r"(w)); return f;
}
__device__ __forceinline__ void ldsm4(u32* r, u32 a) {
    asm volatile("ldmatrix.sync.aligned.m8n8.x4.shared.b16 {%0,%1,%2,%3}, [%4];"
        : "=r"(r[0]), "=r"(r[1]), "=r"(r[2]), "=r"(r[3]) : "r"(a));
}
__device__ __forceinline__ void ldsm2(u32* r, u32 a) {
    asm volatile("ldmatrix.sync.aligned.m8n8.x2.shared.b16 {%0,%1}, [%2];"
        : "=r"(r[0]), "=r"(r[1]) : "r"(a));
}
__device__ __forceinline__ void mma_f16(float* c, const u32* a, const u32* b) {
    asm volatile("mma.sync.aligned.m16n8k16.row.col.f32.f16.f16.f32 "
        "{%0,%1,%2,%3}, {%4,%5,%6,%7}, {%8,%9}, {%0,%1,%2,%3};"
        : "+f"(c[0]), "+f"(c[1]), "+f"(c[2]), "+f"(c[3])
        : "r"(a[0]), "r"(a[1]), "r"(a[2]), "r"(a[3]), "r"(b[0]), "r"(b[1]));
}
__device__ __forceinline__ void cpa16(u32 dst, const void* src) {
    asm volatile("cp.async.cg.shared.global [%0], [%1], 16;" :: "r"(dst), "l"(src));
}
#define CPA_COMMIT() asm volatile("cp.async.commit_group;" ::: "memory")
#define CPA_WAIT0()  asm volatile("cp.async.wait_group 0;" ::: "memory")

__device__ __forceinline__ float ex2f(float t) {
    float r; asm("ex2.approx.f32 %0, %1;" : "=f"(r) : "f"(t)); return r;
}
// C accumulators are pre-biased by -SHIFT; clamp keeps fp16 P finite.
__device__ __forceinline__ float ex2c(float t) {
    return ex2f(fminf(t, CLMP));
}

// ---------------- Kernel 0: x -> transposed fp16 hi/lo [sb][n][c] ----------------
struct XArgs { const float* x[2]; };

__global__ __launch_bounds__(256) void xcvt_kernel(XArgs A)
{
    int n0 = blockIdx.x * 128;
    int sb = blockIdx.y;
    int sel = sb >> 1, b = sb & 1;
    const float* x = A.x[sel] + (size_t)b * Cc * Nn;
    __shared__ float T[64][132];
    int tid = threadIdx.x;

    for (int c0 = 0; c0 < Cc; c0 += 64) {
        int nn = tid & 127, ch = tid >> 7;
        #pragma unroll 8
        for (int i = 0; i < 32; ++i)
            T[ch + 2*i][nn] = x[(size_t)(c0 + ch + 2*i) * Nn + n0 + nn];
        __syncthreads();
        int n = tid >> 1, kh = (tid & 1) * 32;
        u32 hb[16], lb[16];
        #pragma unroll
        for (int j = 0; j < 16; ++j) {
            float v0 = T[kh + 2*j][n], v1 = T[kh + 2*j + 1][n];
            u32 hh = cvt2h(v1, v0);
            hb[j] = hh;
            lb[j] = cvt2h(v1 - hhi(hh), v0 - hlo(hh));
        }
        size_t off = ((size_t)sb * Nn + n0 + n) * Cc + c0 + kh;
        uint4* dh = (uint4*)(g_xTh + off);
        uint4* dl = (uint4*)(g_xTl + off);
        dh[0] = make_uint4(hb[0],hb[1],hb[2],hb[3]);
        dh[1] = make_uint4(hb[4],hb[5],hb[6],hb[7]);
        dh[2] = make_uint4(hb[8],hb[9],hb[10],hb[11]);
        dh[3] = make_uint4(hb[12],hb[13],hb[14],hb[15]);
        dl[0] = make_uint4(lb[0],lb[1],lb[2],lb[3]);
        dl[1] = make_uint4(lb[4],lb[5],lb[6],lb[7]);
        dl[2] = make_uint4(lb[8],lb[9],lb[10],lb[11]);
        dl[3] = make_uint4(lb[12],lb[13],lb[14],lb[15]);
        __syncthreads();
    }
}

// ---------------- Kernel 1: grouped projections via fp16 mma ----------------
struct PjArgs {
    const float* w[2][3];
    const float* bias[2][3];
};

__global__ __launch_bounds__(128) void projmma_kernel(PjArgs A)
{
    __shared__ __align__(16) union {
        struct {
            u16 Ah[64*40], Al[64*40];
            u16 Bh[128*40], Bl[128*40];
        } m;
        float Cd[64*132];
    } SM;

    int tid = threadIdx.x, lane = tid & 31, wid = tid >> 5;
    int n0 = blockIdx.x * 128;
    int jt = blockIdx.y;
    int sb = blockIdx.z, sel = sb >> 1;
    int p  = jt >> 1;
    int g0 = (jt & 1) * 4;

    const float* wsrc = A.w[sel][p] + (size_t)(g0 * CGd) * Cc;
    const u16* xh = g_xTh + (size_t)sb * Nn * Cc;
    const u16* xl = g_xTl + (size_t)sb * Nn * Cc;

    float C[16][4];
    #pragma unroll
    for (int i = 0; i < 16; ++i)
        #pragma unroll
        for (int q = 0; q < 4; ++q) C[i][q] = 0.f;

    u32 AhB = smem_u32(SM.m.Ah), AlB = smem_u32(SM.m.Al);
    u32 BhB = smem_u32(SM.m.Bh), BlB = smem_u32(SM.m.Bl);

    int ar  = (lane & 7) + ((lane >> 3) & 1) * 8;
    int acb = (lane >> 4) * 16;
    int brow = (lane & 7) + ((lane >> 4) & 1) * 8;
    int bcb  = ((lane >> 3) & 1) * 16;

    for (int c0 = 0; c0 < Cc; c0 += 32) {
        {
            int j = tid >> 1, kh2 = (tid & 1) * 16;
            const float* wr = wsrc + (size_t)j * Cc + c0 + kh2;
            u32 hb[8], lb[8];
            #pragma unroll
            for (int q = 0; q < 8; ++q) {
                float v0 = wr[2*q], v1 = wr[2*q + 1];
                u32 hh = cvt2h(v1, v0);
                hb[q] = hh;
                lb[q] = cvt2h(v1 - hhi(hh), v0 - hlo(hh));
            }
            uint4* dh = (uint4*)(SM.m.Ah + j * 40 + kh2);
            uint4* dl = (uint4*)(SM.m.Al + j * 40 + kh2);
            dh[0] = make_uint4(hb[0],hb[1],hb[2],hb[3]);
            dh[1] = make_uint4(hb[4],hb[5],hb[6],hb[7]);
            dl[0] = make_uint4(lb[0],lb[1],lb[2],lb[3]);
            dl[1] = make_uint4(lb[4],lb[5],lb[6],lb[7]);
        }
        {
            size_t off = (size_t)(n0 + tid) * Cc + c0;
            const uint4* sh = (const uint4*)(xh + off);
            const uint4* sl = (const uint4*)(xl + off);
            uint4* dh = (uint4*)(SM.m.Bh + tid * 40);
            uint4* dl = (uint4*)(SM.m.Bl + tid * 40);
            dh[0]=sh[0]; dh[1]=sh[1]; dh[2]=sh[2]; dh[3]=sh[3];
            dl[0]=sl[0]; dl[1]=sl[1]; dl[2]=sl[2]; dl[3]=sl[3];
        }
        __syncthreads();

        #pragma unroll
        for (int kk = 0; kk < 2; ++kk) {
            u32 ah[4], al[4];
            u32 aoff = (u32)(wid*16 + ar) * 80 + kk*32 + acb;
            ldsm4(ah, AhB + aoff);
            ldsm4(al, AlB + aoff);
            #pragma unroll
            for (int nn = 0; nn < 8; ++nn) {
                u32 bh[4], bl[4];
                u32 boff = (u32)(nn*16 + brow) * 80 + kk*32 + bcb;
                ldsm4(bh, BhB + boff);
                ldsm4(bl, BlB + boff);
                mma_f16(C[2*nn],   ah, bh);
                mma_f16(C[2*nn],   al, bh);
                mma_f16(C[2*nn],   ah, bl);
                mma_f16(C[2*nn+1], ah, bh+2);
                mma_f16(C[2*nn+1], al, bh+2);
                mma_f16(C[2*nn+1], ah, bl+2);
            }
        }
        __syncthreads();
    }

    {
        int gq = lane >> 2, tg = lane & 3;
        #pragma unroll
        for (int nf = 0; nf < 16; ++nf) {
            int r = wid*16 + gq, col = nf*8 + 2*tg;
            *(float2*)&SM.Cd[r*132 + col]       = make_float2(C[nf][0], C[nf][1]);
            *(float2*)&SM.Cd[(r+8)*132 + col]   = make_float2(C[nf][2], C[nf][3]);
        }
    }
    __syncthreads();

    if (p < 2) {
        const float* bias = A.bias[sel][p];
        #pragma unroll
        for (int gg = 0; gg < 4; ++gg) {
            int gabs = g0 + gg;
            int bg = sb * Gg + gabs;
            u32 hb[8], lb[8];
            #pragma unroll
            for (int q = 0; q < 8; ++q) {
                float v0 = SM.Cd[(gg*16 + 2*q)*132 + tid]   + bias[gabs*CGd + 2*q];
                float v1 = SM.Cd[(gg*16 + 2*q+1)*132 + tid] + bias[gabs*CGd + 2*q + 1];
                if (p == 0) { v0 *= LOG2E; v1 *= LOG2E; }
                u32 hh = cvt2h(v1, v0);
                hb[q] = hh;
                lb[q] = cvt2h(v1 - hhi(hh), v0 - hlo(hh));
            }
            u16* dst = (p == 0 ? g_thQ : g_phK) + (size_t)(bg * Nn + n0 + tid) * 32;
            uint4* d4 = (uint4*)dst;
            d4[0] = make_uint4(hb[0],hb[1],hb[2],hb[3]);
            d4[1] = make_uint4(hb[4],hb[5],hb[6],hb[7]);
            d4[2] = make_uint4(lb[0],lb[1],lb[2],lb[3]);
            d4[3] = make_uint4(lb[4],lb[5],lb[6],lb[7]);
        }
    } else {
        const float* bias = A.bias[sel][2];
        int half = tid >> 6, np = tid & 63;
        #pragma unroll 4
        for (int rr = 0; rr < 32; ++rr) {
            int j = rr*2 + half;
            int gabs = g0 + (j >> 4), d = j & 15;
            float bv = bias[gabs*CGd + d];
            float v0 = SM.Cd[j*132 + 2*np]     + bv;
            float v1 = SM.Cd[j*132 + 2*np + 1] + bv;
            u32 hh = cvt2h(v1, v0);
            size_t off = ((size_t)(sb*Gg + gabs)*CGd + d) * Nn + n0 + 2*np;
            *(u32*)(g_vH + off) = hh;
            *(u32*)(g_vL + off) = cvt2h(v1 - hhi(hh), v0 - hlo(hh));
        }
    }
}

// ---------------- Kernel 2: fp16 mma flash attention (M-tile 128) ----------------
// cp.async double-buffered K/V; P = fp16(ex2(min(S-16,14))); ones-column softmax.
// C accumulators initialized to -SHIFT (fold of the score shift).
#define OQ    0
#define OBUF  10240
#define BUFSZ 21120
#define OK_   0
#define OVH_  10240
#define OVL_  16768
#define SMSZ  (OBUF + 2*BUFSZ)      // 52480 bytes (dynamic)

__global__ __launch_bounds__(128, 4) void attn_mma_kernel()
{
    extern __shared__ __align__(16) char SM[];

    int tid = threadIdx.x, lane = tid & 31, wid = tid >> 5;
    int g = blockIdx.y, sbz = blockIdx.z;
    int bg = sbz * Gg + g;
    int n0 = blockIdx.x * 128;

    const u16* thq = g_thQ + (size_t)bg * Nn * 32;
    const u16* phk = g_phK + (size_t)bg * Nn * 32;
    const u16* vh  = g_vH + (size_t)bg * CGd * Nn;
    const u16* vl  = g_vL + (size_t)bg * CGd * Nn;

    u32 SMB = smem_u32(SM);
    u32 QB  = SMB + OQ;

    // Q fill: 128 rows
    {
        const uint4* src = (const uint4*)(thq + (size_t)(n0 + tid) * 32);
        uint4* dst = (uint4*)((u16*)(SM + OQ) + tid * 40);
        dst[0] = src[0]; dst[1] = src[1]; dst[2] = src[2]; dst[3] = src[3];
    }
    // VH constant rows 16..23 in BOTH buffers (row 16 = ones)
    #pragma unroll
    for (int b = 0; b < 2; ++b) {
        u16* VHs = (u16*)(SM + OBUF + b * BUFSZ + OVH_);
        #pragma unroll
        for (int i = 0; i < 8; ++i) {
            int r = 16 + i;
            VHs[r * 136 + tid] = (r == 16) ? (u16)0x3C00 : (u16)0;   // fp16 1.0
        }
    }

    int fd = tid >> 3, fblk = (tid & 7) * 16;

    // prologue: fill tile 0 into buffer 0
    {
        u32 base = SMB + OBUF;
        const u16* ks = phk + (size_t)tid * 32;
        u32 kd = base + OK_ + (u32)tid * 80;
        cpa16(kd, ks); cpa16(kd + 16, ks + 8);
        cpa16(kd + 32, ks + 16); cpa16(kd + 48, ks + 24);
        const u16* vhs = vh + (size_t)fd * Nn + fblk;
        const u16* vls = vl + (size_t)fd * Nn + fblk;
        u32 vhd = base + OVH_ + (u32)fd * 272 + (u32)fblk * 2;
        u32 vld = base + OVL_ + (u32)fd * 272 + (u32)fblk * 2;
        cpa16(vhd, vhs); cpa16(vhd + 16, vhs + 8);
        cpa16(vld, vls); cpa16(vld + 16, vls + 8);
        CPA_COMMIT();
    }
    CPA_WAIT0();
    __syncthreads();

    // Q A-fragments: each warp owns 32 query rows (2 x m16)
    u32 qh[2][4], ql[2][4];
    {
        int ar  = (lane & 7) + ((lane >> 3) & 1) * 8;
        int acb = (lane >> 4) * 16;
        #pragma unroll
        for (int mi = 0; mi < 2; ++mi) {
            u32 ad = QB + (u32)(wid * 32 + mi * 16 + ar) * 80 + acb;
            ldsm4(qh[mi], ad);
            ldsm4(ql[mi], ad + 32);
        }
    }

    float O[2][3][4];
    #pragma unroll
    for (int mi = 0; mi < 2; ++mi)
        #pragma unroll
        for (int nt = 0; nt < 3; ++nt)
            #pragma unroll
            for (int q = 0; q < 4; ++q) O[mi][nt][q] = 0.f;

    int krow = (lane & 7) + ((lane >> 4) & 1) * 8;
    int kcb  = ((lane >> 3) & 1) * 16;
    int vrow = (lane & 7);
    int vcb  = ((lane >> 3) & 1) * 16;

    for (int t = 0; t < 18; ++t) {
        u32 cur = SMB + OBUF + (u32)(t & 1) * BUFSZ;

        if (t < 17) {
            u32 base = SMB + OBUF + (u32)((t + 1) & 1) * BUFSZ;
            int t0n = (t + 1) * 128;
            const u16* ks = phk + (size_t)(t0n + tid) * 32;
            u32 kd = base + OK_ + (u32)tid * 80;
            cpa16(kd, ks); cpa16(kd + 16, ks + 8);
            cpa16(kd + 32, ks + 16); cpa16(kd + 48, ks + 24);
            const u16* vhs = vh + (size_t)fd * Nn + t0n + fblk;
            const u16* vls = vl + (size_t)fd * Nn + t0n + fblk;
            u32 vhd = base + OVH_ + (u32)fd * 272 + (u32)fblk * 2;
            u32 vld = base + OVL_ + (u32)fd * 272 + (u32)fblk * 2;
            cpa16(vhd, vhs); cpa16(vhd + 16, vhs + 8);
            cpa16(vld, vls); cpa16(vld + 16, vls + 8);
            CPA_COMMIT();
        }

        u32 KB = cur + OK_, VHB = cur + OVH_, VLB = cur + OVL_;

        #pragma unroll 2
        for (int c = 0; c < 8; ++c) {
            u32 khb4[4], klb4[4];
            {
                u32 a = KB + (u32)(c * 16 + krow) * 80 + kcb;
                ldsm4(khb4, a);
                ldsm4(klb4, a + 32);
            }
            float C[2][2][4];
            #pragma unroll
            for (int mi = 0; mi < 2; ++mi)
                #pragma unroll
                for (int s = 0; s < 2; ++s) {
                    C[mi][s][0] = -SHIFT; C[mi][s][1] = -SHIFT;
                    C[mi][s][2] = -SHIFT; C[mi][s][3] = -SHIFT;
                    mma_f16(C[mi][s], qh[mi], khb4 + 2*s);
                    mma_f16(C[mi][s], qh[mi], klb4 + 2*s);
                    mma_f16(C[mi][s], ql[mi], khb4 + 2*s);
                }
            u32 pha[2][4];
            #pragma unroll
            for (int mi = 0; mi < 2; ++mi)
                #pragma unroll
                for (int s = 0; s < 2; ++s) {
                    float p0 = ex2c(C[mi][s][0]);
                    float p1 = ex2c(C[mi][s][1]);
                    float p2 = ex2c(C[mi][s][2]);
                    float p3 = ex2c(C[mi][s][3]);
                    pha[mi][2*s]     = cvt2h(p1, p0);
                    pha[mi][2*s + 1] = cvt2h(p3, p2);
                }
            u32 vhbf[3][2], vlbf[2][2];
            {
                u32 vbase = (u32)vrow * 272 + (u32)vcb + (u32)c * 32;
                #pragma unroll
                for (int nt = 0; nt < 3; ++nt)
                    ldsm2(vhbf[nt], VHB + vbase + (u32)nt * 8 * 272);
                #pragma unroll
                for (int nt = 0; nt < 2; ++nt)
                    ldsm2(vlbf[nt], VLB + vbase + (u32)nt * 8 * 272);
            }
            #pragma unroll
            for (int mi = 0; mi < 2; ++mi) {
                #pragma unroll
                for (int nt = 0; nt < 3; ++nt)
                    mma_f16(O[mi][nt], pha[mi], vhbf[nt]);
                #pragma unroll
                for (int nt = 0; nt < 2; ++nt)
                    mma_f16(O[mi][nt], pha[mi], vlbf[nt]);
            }
        }

        if (t < 17) CPA_WAIT0();
        __syncthreads();
    }

    // Epilogue: dump O to smem (stride 26), normalize, emit fp16 hi/lo [n][i]
    float* Es = (float*)(SM + OBUF);
    {
        int gq = lane >> 2, tg = lane & 3;
        #pragma unroll
        for (int mi = 0; mi < 2; ++mi)
            #pragma unroll
            for (int nt = 0; nt < 3; ++nt) {
                int r = wid * 32 + mi * 16 + gq;
                int col = nt * 8 + 2 * tg;
                Es[r * 26 + col]           = O[mi][nt][0];
                Es[r * 26 + col + 1]       = O[mi][nt][1];
                Es[(r + 8) * 26 + col]     = O[mi][nt][2];
                Es[(r + 8) * 26 + col + 1] = O[mi][nt][3];
            }
    }
    __syncthreads();
    {
        float inv = 1.0f / Es[tid * 26 + 16];
        u32 hb[8], lb[8];
        #pragma unroll
        for (int q = 0; q < 8; ++q) {
            float v0 = Es[tid * 26 + 2*q]     * inv;
            float v1 = Es[tid * 26 + 2*q + 1] * inv;
            u32 hh = cvt2h(v1, v0);
            hb[q] = hh;
            lb[q] = cvt2h(v1 - hhi(hh), v0 - hlo(hh));
        }
        size_t off = ((size_t)sbz * Nn + n0 + tid) * INTER + g * CGd;
        uint4* dh = (uint4*)(g_ocTh + off);
        uint4* dl = (uint4*)(g_ocTl + off);
        dh[0] = make_uint4(hb[0],hb[1],hb[2],hb[3]);
        dh[1] = make_uint4(hb[4],hb[5],hb[6],hb[7]);
        dl[0] = make_uint4(lb[0],lb[1],lb[2],lb[3]);
        dl[1] = make_uint4(lb[4],lb[5],lb[6],lb[7]);
    }
}

// ---------------- Kernel 3: W conv via fp16 mma (n-tile 128) ----------------
struct WcArgs { const float* Ww[2]; const float* Wb[2]; };

__global__ __launch_bounds__(128) void wconvmma_kernel(WcArgs A)
{
    __shared__ __align__(16) struct {
        u16 Ah[64*40], Al[64*40];
        u16 Bh[128*40], Bl[128*40];
    } SM;

    int tid = threadIdx.x, lane = tid & 31, wid = tid >> 5;
    int n0 = blockIdx.x * 128;
    int o0 = blockIdx.y * 64;
    int sb = blockIdx.z, sel = sb >> 1;

    const float* Ww = A.Ww[sel];
    const u16* och = g_ocTh + (size_t)sb * Nn * INTER;
    const u16* ocl = g_ocTl + (size_t)sb * Nn * INTER;

    float C[16][4];
    #pragma unroll
    for (int i = 0; i < 16; ++i)
        #pragma unroll
        for (int q = 0; q < 4; ++q) C[i][q] = 0.f;

    u32 AhB = smem_u32(SM.Ah), AlB = smem_u32(SM.Al);
    u32 BhB = smem_u32(SM.Bh), BlB = smem_u32(SM.Bl);

    int ar  = (lane & 7) + ((lane >> 3) & 1) * 8;
    int acb = (lane >> 4) * 16;
    int brow = (lane & 7) + ((lane >> 4) & 1) * 8;
    int bcb  = ((lane >> 3) & 1) * 16;

    for (int c0 = 0; c0 < INTER; c0 += 32) {
        {
            int j = tid >> 1, kh2 = (tid & 1) * 16;
            const float* wr = Ww + (size_t)(o0 + j) * INTER + c0 + kh2;
            u32 hb[8], lb[8];
            #pragma unroll
            for (int q = 0; q < 8; ++q) {
                float v0 = wr[2*q], v1 = wr[2*q + 1];
                u32 hh = cvt2h(v1, v0);
                hb[q] = hh;
                lb[q] = cvt2h(v1 - hhi(hh), v0 - hlo(hh));
            }
            uint4* dh = (uint4*)(SM.Ah + j * 40 + kh2);
            uint4* dl = (uint4*)(SM.Al + j * 40 + kh2);
            dh[0] = make_uint4(hb[0],hb[1],hb[2],hb[3]);
            dh[1] = make_uint4(hb[4],hb[5],hb[6],hb[7]);
            dl[0] = make_uint4(lb[0],lb[1],lb[2],lb[3]);
            dl[1] = make_uint4(lb[4],lb[5],lb[6],lb[7]);
        }
        {
            size_t off = (size_t)(n0 + tid) * INTER + c0;
            const uint4* sh = (const uint4*)(och + off);
            const uint4* sl = (const uint4*)(ocl + off);
            uint4* dh = (uint4*)(SM.Bh + tid * 40);
            uint4* dl = (uint4*)(SM.Bl + tid * 40);
            dh[0]=sh[0]; dh[1]=sh[1]; dh[2]=sh[2]; dh[3]=sh[3];
            dl[0]=sl[0]; dl[1]=sl[1]; dl[2]=sl[2]; dl[3]=sl[3];
        }
        __syncthreads();

        #pragma unroll
        for (int kk = 0; kk < 2; ++kk) {
            u32 ah[4], al[4];
            u32 aoff = (u32)(wid*16 + ar) * 80 + kk*32 + acb;
            ldsm4(ah, AhB + aoff);
            ldsm4(al, AlB + aoff);
            #pragma unroll
            for (int nn = 0; nn < 8; ++nn) {
                u32 bh[4], bl[4];
                u32 boff = (u32)(nn*16 + brow) * 80 + kk*32 + bcb;
                ldsm4(bh, BhB + boff);
                ldsm4(bl, BlB + boff);
                mma_f16(C[2*nn],   ah, bh);
                mma_f16(C[2*nn],   al, bh);
                mma_f16(C[2*nn],   ah, bl);
                mma_f16(C[2*nn+1], ah, bh+2);
                mma_f16(C[2*nn+1], al, bh+2);
                mma_f16(C[2*nn+1], ah, bl+2);
            }
        }
        __syncthreads();
    }

    {
        const float* Wb = A.Wb[sel];
        int gq = lane >> 2, tg = lane & 3;
        int o_r = o0 + wid*16 + gq;
        float b0 = Wb[o_r], b1 = Wb[o_r + 8];
        #pragma unroll
        for (int nf = 0; nf < 16; ++nf) {
            int n_c = n0 + nf*8 + 2*tg;
            *(float2*)&g_wy[((size_t)sb*Cc + o_r) * Nn + n_c] =
                make_float2(C[nf][0] + b0, C[nf][1] + b0);
            *(float2*)&g_wy[((size_t)sb*Cc + o_r + 8) * Nn + n_c] =
                make_float2(C[nf][2] + b1, C[nf][3] + b1);
        }
    }
}

// ---------------- Kernel 4: BN stats ----------------
__global__ __launch_bounds__(256) void stats_kernel()
{
    int sel = blockIdx.x / Cc;
    int o   = blockIdx.x % Cc;
    int tid = threadIdx.x;
    const float4* r0 = (const float4*)(g_wy + ((size_t)(sel*Bb + 0) * Cc + o) * Nn);
    const float4* r1 = (const float4*)(g_wy + ((size_t)(sel*Bb + 1) * Cc + o) * Nn);

    float s = 0.f, s2 = 0.f;
    for (int i = tid; i < Nn/4; i += 256) {
        float4 a = r0[i], c = r1[i];
        s += a.x + a.y + a.z + a.w;
        s += c.x + c.y + c.z + c.w;
        s2 = fmaf(a.x, a.x, s2); s2 = fmaf(a.y, a.y, s2);
        s2 = fmaf(a.z, a.z, s2); s2 = fmaf(a.w, a.w, s2);
        s2 = fmaf(c.x, c.x, s2); s2 = fmaf(c.y, c.y, s2);
        s2 = fmaf(c.z, c.z, s2); s2 = fmaf(c.w, c.w, s2);
    }
    __shared__ float sh[256], sh2[256];
    sh[tid] = s; sh2[tid] = s2;
    __syncthreads();
    for (int st = 128; st > 0; st >>= 1) {
        if (tid < st) { sh[tid] += sh[tid + st]; sh2[tid] += sh2[tid + st]; }
        __syncthreads();
    }
    if (tid == 0) {
        float mean = sh[0] * (1.0f / (Bb * Nn));
        float var  = sh2[0] * (1.0f / (Bb * Nn)) - mean * mean;
        g_mean[blockIdx.x] = mean;
        g_rstd[blockIdx.x] = rsqrtf(var + EPSf);
    }
}

// ---------------- Kernel 5: BN apply + residual + ReLU ----------------
struct ApplyArgs {
    const float* x[2];
    const float* gam[2]; const float* bet[2];
};

__global__ __launch_bounds__(256) void apply_kernel(ApplyArgs A, float* __restrict__ out)
{
    int i4 = blockIdx.x * 256 + threadIdx.x;
    int idx = i4 * 4;
    int per = Bb * Cc * Nn;
    int sel = idx / per;
    int loc = idx - sel * per;
    int o   = (loc / Nn) % Cc;
    float m  = g_mean[sel*Cc + o];
    float rs = g_rstd[sel*Cc + o];
    float ga = A.gam[sel][o], be = A.bet[sel][o];
    float4 wv = *(const float4*)(g_wy + idx);
    float4 xv = *(const float4*)(A.x[sel] + loc);
    float4 r;
    r.x = fmaxf(fmaf((wv.x - m) * rs, ga, be) + xv.x, 0.f);
    r.y = fmaxf(fmaf((wv.y - m) * rs, ga, be) + xv.y, 0.f);
    r.z = fmaxf(fmaf((wv.z - m) * rs, ga, be) + xv.z, 0.f);
    r.w = fmaxf(fmaf((wv.w - m) * rs, ga, be) + xv.w, 0.f);
    *(float4*)(out + idx) = r;
}

// ---------------- launch ----------------
extern "C" void kernel_launch(void* const* d_in, const int* in_sizes, int n_in,
                              void* d_out, int out_size)
{
    XArgs X; PjArgs P; WcArgs W; ApplyArgs AP;
    for (int s = 0; s < 2; ++s) {
        X.x[s] = (const float*)d_in[s];
        P.w[s][0]    = (const float*)d_in[2 + s*10 + 2];
        P.bias[s][0] = (const float*)d_in[2 + s*10 + 3];
        P.w[s][1]    = (const float*)d_in[2 + s*10 + 4];
        P.bias[s][1] = (const float*)d_in[2 + s*10 + 5];
        P.w[s][2]    = (const float*)d_in[2 + s*10 + 0];
        P.bias[s][2] = (const float*)d_in[2 + s*10 + 1];
        W.Ww[s] = (const float*)d_in[2 + s*10 + 6];
        W.Wb[s] = (const float*)d_in[2 + s*10 + 7];
        AP.x[s]   = (const float*)d_in[s];
        AP.gam[s] = (const float*)d_in[2 + s*10 + 8];
        AP.bet[s] = (const float*)d_in[2 + s*10 + 9];
    }

    static int attr_set = 0;
    if (!attr_set) {
        cudaFuncSetAttribute(attn_mma_kernel,
                             cudaFuncAttributeMaxDynamicSharedMemorySize, SMSZ);
        attr_set = 1;
    }

    xcvt_kernel    <<<dim3(18, 4), 256>>>(X);
    projmma_kernel <<<dim3(18, 6, 4), 128>>>(P);
    attn_mma_kernel<<<dim3(18, Gg, SEL*Bb), 128, SMSZ>>>();
    wconvmma_kernel<<<dim3(18, 4, 4), 128>>>(W);
    stats_kernel   <<<SEL*Cc, 256>>>();
    apply_kernel   <<<(SEL*Bb*Cc*Nn)/1024, 256>>>(AP, (float*)d_out);
}

// round 17
// speedup vs baseline: 1.3436x; 1.0747x over previous
#include <cuda_runtime.h>
#include <cstdint>

typedef unsigned int u32;
typedef unsigned short u16;

#define SEL   2
#define Bb    2
#define Cc    256
#define Nn    2304
#define Gg    8
#define CGd   16
#define INTER 128
#define EPSf  1e-5f
#define LOG2E 1.4426950408889634f
#define SHIFT 16.0f
#define CLMP  14.0f

// ---------------- scratch ----------------
__device__ __align__(16) u16  g_xTh[SEL*Bb*Nn*Cc];
__device__ __align__(16) u16  g_xTl[SEL*Bb*Nn*Cc];
__device__ __align__(16) u16  g_wtH[8*32768];          // [sel*4 + {tw,pw,gw,Ww}] fp16 hi
__device__ __align__(16) u16  g_wtL[8*32768];          // lo
__device__ __align__(16) u16  g_thQ[SEL*Bb*Gg*Nn*32];
__device__ __align__(16) u16  g_phK[SEL*Bb*Gg*Nn*32];
__device__ __align__(16) u16  g_vH [SEL*Bb*Gg*CGd*Nn];
__device__ __align__(16) u16  g_vL [SEL*Bb*Gg*CGd*Nn];
__device__ __align__(16) u16  g_ocTh[SEL*Bb*Nn*INTER];
__device__ __align__(16) u16  g_ocTl[SEL*Bb*Nn*INTER];
__device__ float g_wy  [SEL*Bb*Cc*Nn];
__device__ float g_mean[SEL*Cc];
__device__ float g_rstd[SEL*Cc];

// ---------------- helpers ----------------
__device__ __forceinline__ u32 smem_u32(const void* p) {
    u32 a;
    asm("{ .reg .u64 t; cvta.to.shared.u64 t, %1; cvt.u32.u64 %0, t; }" : "=r"(a) : "l"(p));
    return a;
}
__device__ __forceinline__ u32 cvt2h(float hi, float lo) {
    u32 d; asm("cvt.rn.f16x2.f32 %0, %1, %2;" : "=r"(d) : "f"(hi), "f"(lo)); return d;
}
__device__ __forceinline__ float hlo(u32 w) {
    float f; asm("{.reg .b16 a,b; mov.b32 {a,b}, %1; cvt.f32.f16 %0, a;}" : "=f"(f) : "r"(w)); return f;
}
__device__ __forceinline__ float hhi(u32 w) {
    float f; asm("{.reg .b16 a,b; mov.b32 {a,b}, %1; cvt.f32.f16 %0, b;}" : "=f"(f) : "r"(w)); return f;
}
__device__ __forceinline__ void ldsm4(u32* r, u32 a) {
    asm volatile("ldmatrix.sync.aligned.m8n8.x4.shared.b16 {%0,%1,%2,%3}, [%4];"
        : "=r"(r[0]), "=r"(r[1]), "=r"(r[2]), "=r"(r[3]) : "r"(a));
}
__device__ __forceinline__ void ldsm2(u32* r, u32 a) {
    asm volatile("ldmatrix.sync.aligned.m8n8.x2.shared.b16 {%0,%1}, [%2];"
        : "=r"(r[0]), "=r"(r[1]) : "r"(a));
}
__device__ __forceinline__ void mma_f16(float* c, const u32* a, const u32* b) {
    asm volatile("mma.sync.aligned.m16n8k16.row.col.f32.f16.f16.f32 "
        "{%0,%1,%2,%3}, {%4,%5,%6,%7}, {%8,%9}, {%0,%1,%2,%3};"
        : "+f"(c[0]), "+f"(c[1]), "+f"(c[2]), "+f"(c[3])
        : "r"(a[0]), "r"(a[1]), "r"(a[2]), "r"(a[3]), "r"(b[0]), "r"(b[1]));
}
__device__ __forceinline__ void cpa16(u32 dst, const void* src) {
    asm volatile("cp.async.cg.shared.global [%0], [%1], 16;" :: "r"(dst), "l"(src));
}
#define CPA_COMMIT() asm volatile("cp.async.commit_group;" ::: "memory")
#define CPA_WAIT0()  asm volatile("cp.async.wait_group 0;" ::: "memory")

__device__ __forceinline__ float ex2f(float t) {
    float r; asm("ex2.approx.f32 %0, %1;" : "=f"(r) : "f"(t)); return r;
}
__device__ __forceinline__ float ex2c(float t) {
    return ex2f(fminf(t, CLMP));
}

// ---------------- Kernel W: one-time weight conversion fp32 -> fp16 hi/lo ----------------
struct WtArgs { const float* src[8]; };   // [sel*4 + {tw,pw,gw,Ww}], each 32768 elems

__global__ __launch_bounds__(256) void wcvt_kernel(WtArgs A)
{
    int arr = blockIdx.y;
    int base = (blockIdx.x * 256 + threadIdx.x) * 4;
    float4 v = *(const float4*)(A.src[arr] + base);
    u32 h0 = cvt2h(v.y, v.x);
    u32 h1 = cvt2h(v.w, v.z);
    u32 l0 = cvt2h(v.y - hhi(h0), v.x - hlo(h0));
    u32 l1 = cvt2h(v.w - hhi(h1), v.z - hlo(h1));
    size_t off = (size_t)arr * 32768 + base;
    *(uint2*)(g_wtH + off) = make_uint2(h0, h1);
    *(uint2*)(g_wtL + off) = make_uint2(l0, l1);
}

// ---------------- Kernel 0: x -> transposed fp16 hi/lo [sb][n][c] ----------------
struct XArgs { const float* x[2]; };

__global__ __launch_bounds__(256) void xcvt_kernel(XArgs A)
{
    int n0 = blockIdx.x * 128;
    int sb = blockIdx.y;
    int sel = sb >> 1, b = sb & 1;
    const float* x = A.x[sel] + (size_t)b * Cc * Nn;
    __shared__ float T[64][132];
    int tid = threadIdx.x;

    for (int c0 = 0; c0 < Cc; c0 += 64) {
        int nn = tid & 127, ch = tid >> 7;
        #pragma unroll 8
        for (int i = 0; i < 32; ++i)
            T[ch + 2*i][nn] = x[(size_t)(c0 + ch + 2*i) * Nn + n0 + nn];
        __syncthreads();
        int n = tid >> 1, kh = (tid & 1) * 32;
        u32 hb[16], lb[16];
        #pragma unroll
        for (int j = 0; j < 16; ++j) {
            float v0 = T[kh + 2*j][n], v1 = T[kh + 2*j + 1][n];
            u32 hh = cvt2h(v1, v0);
            hb[j] = hh;
            lb[j] = cvt2h(v1 - hhi(hh), v0 - hlo(hh));
        }
        size_t off = ((size_t)sb * Nn + n0 + n) * Cc + c0 + kh;
        uint4* dh = (uint4*)(g_xTh + off);
        uint4* dl = (uint4*)(g_xTl + off);
        dh[0] = make_uint4(hb[0],hb[1],hb[2],hb[3]);
        dh[1] = make_uint4(hb[4],hb[5],hb[6],hb[7]);
        dh[2] = make_uint4(hb[8],hb[9],hb[10],hb[11]);
        dh[3] = make_uint4(hb[12],hb[13],hb[14],hb[15]);
        dl[0] = make_uint4(lb[0],lb[1],lb[2],lb[3]);
        dl[1] = make_uint4(lb[4],lb[5],lb[6],lb[7]);
        dl[2] = make_uint4(lb[8],lb[9],lb[10],lb[11]);
        dl[3] = make_uint4(lb[12],lb[13],lb[14],lb[15]);
        __syncthreads();
    }
}

// ---------------- Kernel 1: grouped projections via fp16 mma (cp.async fills) ----------------
struct PjArgs { const float* bias[2][3]; };

__global__ __launch_bounds__(128) void projmma_kernel(PjArgs A)
{
    __shared__ __align__(16) union {
        struct {
            u16 Ah[64*40], Al[64*40];
            u16 Bh[128*40], Bl[128*40];
        } m;
        float Cd[64*132];
    } SM;

    int tid = threadIdx.x, lane = tid & 31, wid = tid >> 5;
    int n0 = blockIdx.x * 128;
    int jt = blockIdx.y;
    int sb = blockIdx.z, sel = sb >> 1;
    int p  = jt >> 1;
    int g0 = (jt & 1) * 4;

    size_t wbase = (size_t)(sel * 4 + p) * 32768 + (size_t)((jt & 1) * 64) * Cc;
    const u16* whs = g_wtH + wbase;
    const u16* wls = g_wtL + wbase;
    const u16* xh = g_xTh + (size_t)sb * Nn * Cc;
    const u16* xl = g_xTl + (size_t)sb * Nn * Cc;

    float C[16][4];
    #pragma unroll
    for (int i = 0; i < 16; ++i)
        #pragma unroll
        for (int q = 0; q < 4; ++q) C[i][q] = 0.f;

    u32 AhB = smem_u32(SM.m.Ah), AlB = smem_u32(SM.m.Al);
    u32 BhB = smem_u32(SM.m.Bh), BlB = smem_u32(SM.m.Bl);

    int ar  = (lane & 7) + ((lane >> 3) & 1) * 8;
    int acb = (lane >> 4) * 16;
    int brow = (lane & 7) + ((lane >> 4) & 1) * 8;
    int bcb  = ((lane >> 3) & 1) * 16;

    int aj = tid >> 1, akh = (tid & 1) * 16;

    for (int c0 = 0; c0 < Cc; c0 += 32) {
        // A fill: cp.async from pre-converted weights
        {
            size_t so = (size_t)aj * Cc + c0 + akh;
            u32 d = (u32)(aj * 80 + akh * 2);
            cpa16(AhB + d, whs + so); cpa16(AhB + d + 16, whs + so + 8);
            cpa16(AlB + d, wls + so); cpa16(AlB + d + 16, wls + so + 8);
        }
        // B fill: cp.async
        {
            size_t off = (size_t)(n0 + tid) * Cc + c0;
            u32 d = BhB + (u32)tid * 80;
            cpa16(d, xh + off);      cpa16(d + 16, xh + off + 8);
            cpa16(d + 32, xh + off + 16); cpa16(d + 48, xh + off + 24);
            d = BlB + (u32)tid * 80;
            cpa16(d, xl + off);      cpa16(d + 16, xl + off + 8);
            cpa16(d + 32, xl + off + 16); cpa16(d + 48, xl + off + 24);
        }
        CPA_COMMIT();
        CPA_WAIT0();
        __syncthreads();

        #pragma unroll
        for (int kk = 0; kk < 2; ++kk) {
            u32 ah[4], al[4];
            u32 aoff = (u32)(wid*16 + ar) * 80 + kk*32 + acb;
            ldsm4(ah, AhB + aoff);
            ldsm4(al, AlB + aoff);
            #pragma unroll
            for (int nn = 0; nn < 8; ++nn) {
                u32 bh[4], bl[4];
                u32 boff = (u32)(nn*16 + brow) * 80 + kk*32 + bcb;
                ldsm4(bh, BhB + boff);
                ldsm4(bl, BlB + boff);
                mma_f16(C[2*nn],   ah, bh);
                mma_f16(C[2*nn],   al, bh);
                mma_f16(C[2*nn],   ah, bl);
                mma_f16(C[2*nn+1], ah, bh+2);
                mma_f16(C[2*nn+1], al, bh+2);
                mma_f16(C[2*nn+1], ah, bl+2);
            }
        }
        __syncthreads();
    }

    {
        int gq = lane >> 2, tg = lane & 3;
        #pragma unroll
        for (int nf = 0; nf < 16; ++nf) {
            int r = wid*16 + gq, col = nf*8 + 2*tg;
            *(float2*)&SM.Cd[r*132 + col]       = make_float2(C[nf][0], C[nf][1]);
            *(float2*)&SM.Cd[(r+8)*132 + col]   = make_float2(C[nf][2], C[nf][3]);
        }
    }
    __syncthreads();

    if (p < 2) {
        const float* bias = A.bias[sel][p];
        #pragma unroll
        for (int gg = 0; gg < 4; ++gg) {
            int gabs = g0 + gg;
            int bg = sb * Gg + gabs;
            u32 hb[8], lb[8];
            #pragma unroll
            for (int q = 0; q < 8; ++q) {
                float v0 = SM.Cd[(gg*16 + 2*q)*132 + tid]   + bias[gabs*CGd + 2*q];
                float v1 = SM.Cd[(gg*16 + 2*q+1)*132 + tid] + bias[gabs*CGd + 2*q + 1];
                if (p == 0) { v0 *= LOG2E; v1 *= LOG2E; }
                u32 hh = cvt2h(v1, v0);
                hb[q] = hh;
                lb[q] = cvt2h(v1 - hhi(hh), v0 - hlo(hh));
            }
            u16* dst = (p == 0 ? g_thQ : g_phK) + (size_t)(bg * Nn + n0 + tid) * 32;
            uint4* d4 = (uint4*)dst;
            d4[0] = make_uint4(hb[0],hb[1],hb[2],hb[3]);
            d4[1] = make_uint4(hb[4],hb[5],hb[6],hb[7]);
            d4[2] = make_uint4(lb[0],lb[1],lb[2],lb[3]);
            d4[3] = make_uint4(lb[4],lb[5],lb[6],lb[7]);
        }
    } else {
        const float* bias = A.bias[sel][2];
        int half = tid >> 6, np = tid & 63;
        #pragma unroll 4
        for (int rr = 0; rr < 32; ++rr) {
            int j = rr*2 + half;
            int gabs = g0 + (j >> 4), d = j & 15;
            float bv = bias[gabs*CGd + d];
            float v0 = SM.Cd[j*132 + 2*np]     + bv;
            float v1 = SM.Cd[j*132 + 2*np + 1] + bv;
            u32 hh = cvt2h(v1, v0);
            size_t off = ((size_t)(sb*Gg + gabs)*CGd + d) * Nn + n0 + 2*np;
            *(u32*)(g_vH + off) = hh;
            *(u32*)(g_vL + off) = cvt2h(v1 - hhi(hh), v0 - hlo(hh));
        }
    }
}

// ---------------- Kernel 2: fp16 mma flash attention (M-tile 128) ----------------
#define OQ    0
#define OBUF  10240
#define BUFSZ 21120
#define OK_   0
#define OVH_  10240
#define OVL_  16768
#define SMSZ  (OBUF + 2*BUFSZ)

__global__ __launch_bounds__(128, 4) void attn_mma_kernel()
{
    extern __shared__ __align__(16) char SM[];

    int tid = threadIdx.x, lane = tid & 31, wid = tid >> 5;
    int g = blockIdx.y, sbz = blockIdx.z;
    int bg = sbz * Gg + g;
    int n0 = blockIdx.x * 128;

    const u16* thq = g_thQ + (size_t)bg * Nn * 32;
    const u16* phk = g_phK + (size_t)bg * Nn * 32;
    const u16* vh  = g_vH + (size_t)bg * CGd * Nn;
    const u16* vl  = g_vL + (size_t)bg * CGd * Nn;

    u32 SMB = smem_u32(SM);
    u32 QB  = SMB + OQ;

    {
        const uint4* src = (const uint4*)(thq + (size_t)(n0 + tid) * 32);
        uint4* dst = (uint4*)((u16*)(SM + OQ) + tid * 40);
        dst[0] = src[0]; dst[1] = src[1]; dst[2] = src[2]; dst[3] = src[3];
    }
    #pragma unroll
    for (int b = 0; b < 2; ++b) {
        u16* VHs = (u16*)(SM + OBUF + b * BUFSZ + OVH_);
        #pragma unroll
        for (int i = 0; i < 8; ++i) {
            int r = 16 + i;
            VHs[r * 136 + tid] = (r == 16) ? (u16)0x3C00 : (u16)0;
        }
    }

    int fd = tid >> 3, fblk = (tid & 7) * 16;

    {
        u32 base = SMB + OBUF;
        const u16* ks = phk + (size_t)tid * 32;
        u32 kd = base + OK_ + (u32)tid * 80;
        cpa16(kd, ks); cpa16(kd + 16, ks + 8);
        cpa16(kd + 32, ks + 16); cpa16(kd + 48, ks + 24);
        const u16* vhs = vh + (size_t)fd * Nn + fblk;
        const u16* vls = vl + (size_t)fd * Nn + fblk;
        u32 vhd = base + OVH_ + (u32)fd * 272 + (u32)fblk * 2;
        u32 vld = base + OVL_ + (u32)fd * 272 + (u32)fblk * 2;
        cpa16(vhd, vhs); cpa16(vhd + 16, vhs + 8);
        cpa16(vld, vls); cpa16(vld + 16, vls + 8);
        CPA_COMMIT();
    }
    CPA_WAIT0();
    __syncthreads();

    u32 qh[2][4], ql[2][4];
    {
        int ar  = (lane & 7) + ((lane >> 3) & 1) * 8;
        int acb = (lane >> 4) * 16;
        #pragma unroll
        for (int mi = 0; mi < 2; ++mi) {
            u32 ad = QB + (u32)(wid * 32 + mi * 16 + ar) * 80 + acb;
            ldsm4(qh[mi], ad);
            ldsm4(ql[mi], ad + 32);
        }
    }

    float O[2][3][4];
    #pragma unroll
    for (int mi = 0; mi < 2; ++mi)
        #pragma unroll
        for (int nt = 0; nt < 3; ++nt)
            #pragma unroll
            for (int q = 0; q < 4; ++q) O[mi][nt][q] = 0.f;

    int krow = (lane & 7) + ((lane >> 4) & 1) * 8;
    int kcb  = ((lane >> 3) & 1) * 16;
    int vrow = (lane & 7);
    int vcb  = ((lane >> 3) & 1) * 16;

    for (int t = 0; t < 18; ++t) {
        u32 cur = SMB + OBUF + (u32)(t & 1) * BUFSZ;

        if (t < 17) {
            u32 base = SMB + OBUF + (u32)((t + 1) & 1) * BUFSZ;
            int t0n = (t + 1) * 128;
            const u16* ks = phk + (size_t)(t0n + tid) * 32;
            u32 kd = base + OK_ + (u32)tid * 80;
            cpa16(kd, ks); cpa16(kd + 16, ks + 8);
            cpa16(kd + 32, ks + 16); cpa16(kd + 48, ks + 24);
            const u16* vhs = vh + (size_t)fd * Nn + t0n + fblk;
            const u16* vls = vl + (size_t)fd * Nn + t0n + fblk;
            u32 vhd = base + OVH_ + (u32)fd * 272 + (u32)fblk * 2;
            u32 vld = base + OVL_ + (u32)fd * 272 + (u32)fblk * 2;
            cpa16(vhd, vhs); cpa16(vhd + 16, vhs + 8);
            cpa16(vld, vls); cpa16(vld + 16, vls + 8);
            CPA_COMMIT();
        }

        u32 KB = cur + OK_, VHB = cur + OVH_, VLB = cur + OVL_;

        #pragma unroll 2
        for (int c = 0; c < 8; ++c) {
            u32 khb4[4], klb4[4];
            {
                u32 a = KB + (u32)(c * 16 + krow) * 80 + kcb;
                ldsm4(khb4, a);
                ldsm4(klb4, a + 32);
            }
            // V fragments hoisted: latency hides under S-MMA + MUFU
            u32 vhbf[3][2], vlbf[2][2];
            {
                u32 vbase = (u32)vrow * 272 + (u32)vcb + (u32)c * 32;
                #pragma unroll
                for (int nt = 0; nt < 3; ++nt)
                    ldsm2(vhbf[nt], VHB + vbase + (u32)nt * 8 * 272);
                #pragma unroll
                for (int nt = 0; nt < 2; ++nt)
                    ldsm2(vlbf[nt], VLB + vbase + (u32)nt * 8 * 272);
            }
            float C[2][2][4];
            #pragma unroll
            for (int mi = 0; mi < 2; ++mi)
                #pragma unroll
                for (int s = 0; s < 2; ++s) {
                    C[mi][s][0] = -SHIFT; C[mi][s][1] = -SHIFT;
                    C[mi][s][2] = -SHIFT; C[mi][s][3] = -SHIFT;
                    mma_f16(C[mi][s], qh[mi], khb4 + 2*s);
                    mma_f16(C[mi][s], qh[mi], klb4 + 2*s);
                    mma_f16(C[mi][s], ql[mi], khb4 + 2*s);
                }
            u32 pha[2][4];
            #pragma unroll
            for (int mi = 0; mi < 2; ++mi)
                #pragma unroll
                for (int s = 0; s < 2; ++s) {
                    float p0 = ex2c(C[mi][s][0]);
                    float p1 = ex2c(C[mi][s][1]);
                    float p2 = ex2c(C[mi][s][2]);
                    float p3 = ex2c(C[mi][s][3]);
                    pha[mi][2*s]     = cvt2h(p1, p0);
                    pha[mi][2*s + 1] = cvt2h(p3, p2);
                }
            #pragma unroll
            for (int mi = 0; mi < 2; ++mi) {
                #pragma unroll
                for (int nt = 0; nt < 3; ++nt)
                    mma_f16(O[mi][nt], pha[mi], vhbf[nt]);
                #pragma unroll
                for (int nt = 0; nt < 2; ++nt)
                    mma_f16(O[mi][nt], pha[mi], vlbf[nt]);
            }
        }

        if (t < 17) CPA_WAIT0();
        __syncthreads();
    }

    float* Es = (float*)(SM + OBUF);
    {
        int gq = lane >> 2, tg = lane & 3;
        #pragma unroll
        for (int mi = 0; mi < 2; ++mi)
            #pragma unroll
            for (int nt = 0; nt < 3; ++nt) {
                int r = wid * 32 + mi * 16 + gq;
                int col = nt * 8 + 2 * tg;
                Es[r * 26 + col]           = O[mi][nt][0];
                Es[r * 26 + col + 1]       = O[mi][nt][1];
                Es[(r + 8) * 26 + col]     = O[mi][nt][2];
                Es[(r + 8) * 26 + col + 1] = O[mi][nt][3];
            }
    }
    __syncthreads();
    {
        float inv = 1.0f / Es[tid * 26 + 16];
        u32 hb[8], lb[8];
        #pragma unroll
        for (int q = 0; q < 8; ++q) {
            float v0 = Es[tid * 26 + 2*q]     * inv;
            float v1 = Es[tid * 26 + 2*q + 1] * inv;
            u32 hh = cvt2h(v1, v0);
            hb[q] = hh;
            lb[q] = cvt2h(v1 - hhi(hh), v0 - hlo(hh));
        }
        size_t off = ((size_t)sbz * Nn + n0 + tid) * INTER + g * CGd;
        uint4* dh = (uint4*)(g_ocTh + off);
        uint4* dl = (uint4*)(g_ocTl + off);
        dh[0] = make_uint4(hb[0],hb[1],hb[2],hb[3]);
        dh[1] = make_uint4(hb[4],hb[5],hb[6],hb[7]);
        dl[0] = make_uint4(lb[0],lb[1],lb[2],lb[3]);
        dl[1] = make_uint4(lb[4],lb[5],lb[6],lb[7]);
    }
}

// ---------------- Kernel 3: W conv via fp16 mma (cp.async fills) ----------------
struct WcArgs { const float* Wb[2]; };

__global__ __launch_bounds__(128) void wconvmma_kernel(WcArgs A)
{
    __shared__ __align__(16) struct {
        u16 Ah[64*40], Al[64*40];
        u16 Bh[128*40], Bl[128*40];
    } SM;

    int tid = threadIdx.x, lane = tid & 31, wid = tid >> 5;
    int n0 = blockIdx.x * 128;
    int o0 = blockIdx.y * 64;
    int sb = blockIdx.z, sel = sb >> 1;

    size_t wbase = (size_t)(sel * 4 + 3) * 32768 + (size_t)o0 * INTER;
    const u16* whs = g_wtH + wbase;
    const u16* wls = g_wtL + wbase;
    const u16* och = g_ocTh + (size_t)sb * Nn * INTER;
    const u16* ocl = g_ocTl + (size_t)sb * Nn * INTER;

    float C[16][4];
    #pragma unroll
    for (int i = 0; i < 16; ++i)
        #pragma unroll
        for (int q = 0; q < 4; ++q) C[i][q] = 0.f;

    u32 AhB = smem_u32(SM.Ah), AlB = smem_u32(SM.Al);
    u32 BhB = smem_u32(SM.Bh), BlB = smem_u32(SM.Bl);

    int ar  = (lane & 7) + ((lane >> 3) & 1) * 8;
    int acb = (lane >> 4) * 16;
    int brow = (lane & 7) + ((lane >> 4) & 1) * 8;
    int bcb  = ((lane >> 3) & 1) * 16;

    int aj = tid >> 1, akh = (tid & 1) * 16;

    for (int c0 = 0; c0 < INTER; c0 += 32) {
        {
            size_t so = (size_t)aj * INTER + c0 + akh;
            u32 d = (u32)(aj * 80 + akh * 2);
            cpa16(AhB + d, whs + so); cpa16(AhB + d + 16, whs + so + 8);
            cpa16(AlB + d, wls + so); cpa16(AlB + d + 16, wls + so + 8);
        }
        {
            size_t off = (size_t)(n0 + tid) * INTER + c0;
            u32 d = BhB + (u32)tid * 80;
            cpa16(d, och + off);       cpa16(d + 16, och + off + 8);
            cpa16(d + 32, och + off + 16); cpa16(d + 48, och + off + 24);
            d = BlB + (u32)tid * 80;
            cpa16(d, ocl + off);       cpa16(d + 16, ocl + off + 8);
            cpa16(d + 32, ocl + off + 16); cpa16(d + 48, ocl + off + 24);
        }
        CPA_COMMIT();
        CPA_WAIT0();
        __syncthreads();

        #pragma unroll
        for (int kk = 0; kk < 2; ++kk) {
            u32 ah[4], al[4];
            u32 aoff = (u32)(wid*16 + ar) * 80 + kk*32 + acb;
            ldsm4(ah, AhB + aoff);
            ldsm4(al, AlB + aoff);
            #pragma unroll
            for (int nn = 0; nn < 8; ++nn) {
                u32 bh[4], bl[4];
                u32 boff = (u32)(nn*16 + brow) * 80 + kk*32 + bcb;
                ldsm4(bh, BhB + boff);
                ldsm4(bl, BlB + boff);
                mma_f16(C[2*nn],   ah, bh);
                mma_f16(C[2*nn],   al, bh);
                mma_f16(C[2*nn],   ah, bl);
                mma_f16(C[2*nn+1], ah, bh+2);
                mma_f16(C[2*nn+1], al, bh+2);
                mma_f16(C[2*nn+1], ah, bl+2);
            }
        }
        __syncthreads();
    }

    {
        const float* Wb = A.Wb[sel];
        int gq = lane >> 2, tg = lane & 3;
        int o_r = o0 + wid*16 + gq;
        float b0 = Wb[o_r], b1 = Wb[o_r + 8];
        #pragma unroll
        for (int nf = 0; nf < 16; ++nf) {
            int n_c = n0 + nf*8 + 2*tg;
            *(float2*)&g_wy[((size_t)sb*Cc + o_r) * Nn + n_c] =
                make_float2(C[nf][0] + b0, C[nf][1] + b0);
            *(float2*)&g_wy[((size_t)sb*Cc + o_r + 8) * Nn + n_c] =
                make_float2(C[nf][2] + b1, C[nf][3] + b1);
        }
    }
}

// ---------------- Kernel 4: BN stats ----------------
__global__ __launch_bounds__(256) void stats_kernel()
{
    int sel = blockIdx.x / Cc;
    int o   = blockIdx.x % Cc;
    int tid = threadIdx.x;
    const float4* r0 = (const float4*)(g_wy + ((size_t)(sel*Bb + 0) * Cc + o) * Nn);
    const float4* r1 = (const float4*)(g_wy + ((size_t)(sel*Bb + 1) * Cc + o) * Nn);

    float s = 0.f, s2 = 0.f;
    for (int i = tid; i < Nn/4; i += 256) {
        float4 a = r0[i], c = r1[i];
        s += a.x + a.y + a.z + a.w;
        s += c.x + c.y + c.z + c.w;
        s2 = fmaf(a.x, a.x, s2); s2 = fmaf(a.y, a.y, s2);
        s2 = fmaf(a.z, a.z, s2); s2 = fmaf(a.w, a.w, s2);
        s2 = fmaf(c.x, c.x, s2); s2 = fmaf(c.y, c.y, s2);
        s2 = fmaf(c.z, c.z, s2); s2 = fmaf(c.w, c.w, s2);
    }
    __shared__ float sh[256], sh2[256];
    sh[tid] = s; sh2[tid] = s2;
    __syncthreads();
    for (int st = 128; st > 0; st >>= 1) {
        if (tid < st) { sh[tid] += sh[tid + st]; sh2[tid] += sh2[tid + st]; }
        __syncthreads();
    }
    if (tid == 0) {
        float mean = sh[0] * (1.0f / (Bb * Nn));
        float var  = sh2[0] * (1.0f / (Bb * Nn)) - mean * mean;
        g_mean[blockIdx.x] = mean;
        g_rstd[blockIdx.x] = rsqrtf(var + EPSf);
    }
}

// ---------------- Kernel 5: BN apply + residual + ReLU ----------------
struct ApplyArgs {
    const float* x[2];
    const float* gam[2]; const float* bet[2];
};

__global__ __launch_bounds__(256) void apply_kernel(ApplyArgs A, float* __restrict__ out)
{
    int i4 = blockIdx.x * 256 + threadIdx.x;
    int idx = i4 * 4;
    int per = Bb * Cc * Nn;
    int sel = idx / per;
    int loc = idx - sel * per;
    int o   = (loc / Nn) % Cc;
    float m  = g_mean[sel*Cc + o];
    float rs = g_rstd[sel*Cc + o];
    float ga = A.gam[sel][o], be = A.bet[sel][o];
    float4 wv = *(const float4*)(g_wy + idx);
    float4 xv = *(const float4*)(A.x[sel] + loc);
    float4 r;
    r.x = fmaxf(fmaf((wv.x - m) * rs, ga, be) + xv.x, 0.f);
    r.y = fmaxf(fmaf((wv.y - m) * rs, ga, be) + xv.y, 0.f);
    r.z = fmaxf(fmaf((wv.z - m) * rs, ga, be) + xv.z, 0.f);
    r.w = fmaxf(fmaf((wv.w - m) * rs, ga, be) + xv.w, 0.f);
    *(float4*)(out + idx) = r;
}

// ---------------- launch ----------------
extern "C" void kernel_launch(void* const* d_in, const int* in_sizes, int n_in,
                              void* d_out, int out_size)
{
    XArgs X; WtArgs WT; PjArgs P; WcArgs W; ApplyArgs AP;
    for (int s = 0; s < 2; ++s) {
        X.x[s] = (const float*)d_in[s];
        WT.src[s*4 + 0] = (const float*)d_in[2 + s*10 + 2];   // theta_w
        WT.src[s*4 + 1] = (const float*)d_in[2 + s*10 + 4];   // phi_w
        WT.src[s*4 + 2] = (const float*)d_in[2 + s*10 + 0];   // g_w
        WT.src[s*4 + 3] = (const float*)d_in[2 + s*10 + 6];   // W_w
        P.bias[s][0] = (const float*)d_in[2 + s*10 + 3];
        P.bias[s][1] = (const float*)d_in[2 + s*10 + 5];
        P.bias[s][2] = (const float*)d_in[2 + s*10 + 1];
        W.Wb[s] = (const float*)d_in[2 + s*10 + 7];
        AP.x[s]   = (const float*)d_in[s];
        AP.gam[s] = (const float*)d_in[2 + s*10 + 8];
        AP.bet[s] = (const float*)d_in[2 + s*10 + 9];
    }

    static int attr_set = 0;
    if (!attr_set) {
        cudaFuncSetAttribute(attn_mma_kernel,
                             cudaFuncAttributeMaxDynamicSharedMemorySize, SMSZ);
        attr_set = 1;
    }

    wcvt_kernel    <<<dim3(32, 8), 256>>>(WT);
    xcvt_kernel    <<<dim3(18, 4), 256>>>(X);
    projmma_kernel <<<dim3(18, 6, 4), 128>>>(P);
    attn_mma_kernel<<<dim3(18, Gg, SEL*Bb), 128, SMSZ>>>();
    wconvmma_kernel<<<dim3(18, 4, 4), 128>>>(W);
    stats_kernel   <<<SEL*Cc, 256>>>();
    apply_kernel   <<<(SEL*Bb*Cc*Nn)/1024, 256>>>(AP, (float*)d_out);
}